// round 2
// baseline (speedup 1.0000x reference)
#include <cuda_runtime.h>
#include <math.h>

#define BB   64
#define LLEN 128
#define CDIM 512
#define DI   1024
#define DS   16
#define DTR  32
#define MROWS (BB*LLEN)   // 8192
#define KCAT  (CDIM*3)    // 1536

// ---------------- scratch (module-load allocated, allowed) ----------------
__device__ float g_fts0[MROWS*CDIM];
__device__ float g_xcat[MROWS*KCAT];
__device__ float g_wcat[CDIM*KCAT];
__device__ float g_conv[MROWS*CDIM];
__device__ float g_F   [MROWS*CDIM];
__device__ float g_xz  [MROWS*2*DI];
__device__ float g_xact[MROWS*DI];
__device__ float g_dbc [MROWS*64];
__device__ float g_dt  [MROWS*DI];
__device__ float g_ys  [MROWS*DI];
__device__ float g_m   [MROWS*CDIM];
__device__ float g_fts2[MROWS*CDIM];
__device__ float g_coff[MROWS];

// ---------------- elementwise / prep kernels ----------------

// fts0[b,l,d]: l<64 from spt (reshape (B,DIM,H,W)->(B,64,512) is a raw reinterpret),
// l>=64 from qry.
__global__ void k_concat(const float* __restrict__ spt, const float* __restrict__ qry) {
    int idx = blockIdx.x * blockDim.x + threadIdx.x;
    if (idx >= MROWS*CDIM) return;
    int b = idx >> 16;       // / (128*512)
    int r = idx & 65535;
    g_fts0[idx] = (r < 32768) ? spt[b*32768 + r] : qry[b*32768 + (r - 32768)];
}

// Wcat[o, k*512+i] = conv_w[o, i, k]   (conv_w shape (512,512,3))
__global__ void k_wcat(const float* __restrict__ cw) {
    int idx = blockIdx.x * blockDim.x + threadIdx.x;
    if (idx >= CDIM*KCAT) return;
    int o = idx / KCAT, kk = idx % KCAT;
    int k = kk >> 9, i = kk & 511;
    g_wcat[idx] = cw[o*KCAT + i*3 + k];
}

// Xcat[(b,l), k*512+i] = fts0[b, l+k-1, i]  (zero pad)
__global__ void k_im2col() {
    int idx = blockIdx.x * blockDim.x + threadIdx.x;
    if (idx >= MROWS*KCAT) return;
    int m = idx / KCAT, kk = idx % KCAT;
    int ks = kk >> 9, i = kk & 511;
    int b = m >> 7, l = m & 127;
    int ll = l + ks - 1;
    g_xcat[idx] = ((unsigned)ll < 128u) ? g_fts0[((b<<7)+ll)*CDIM + i] : 0.f;
}

// LayerNorm over 512 channels at each (b,l); optional residual add; optional relu.
__global__ __launch_bounds__(256) void k_ln(const float* __restrict__ x,
                                            const float* __restrict__ res,
                                            const float* __restrict__ w,
                                            const float* __restrict__ bb,
                                            float* __restrict__ out, int relu)
{
    int row = blockIdx.x;
    size_t base = (size_t)row * CDIM;
    int t = threadIdx.x;
    float a0 = x[base + t], a1 = x[base + t + 256];
    if (res) { a0 += res[base + t]; a1 += res[base + t + 256]; }
    float s = a0 + a1, q = a0*a0 + a1*a1;
    __shared__ float shs[8], shq[8];
    int lane = t & 31, wid = t >> 5;
    #pragma unroll
    for (int o = 16; o; o >>= 1) {
        s += __shfl_xor_sync(0xffffffffu, s, o);
        q += __shfl_xor_sync(0xffffffffu, q, o);
    }
    if (lane == 0) { shs[wid] = s; shq[wid] = q; }
    __syncthreads();
    if (t < 32) {
        s = (lane < 8) ? shs[lane] : 0.f;
        q = (lane < 8) ? shq[lane] : 0.f;
        #pragma unroll
        for (int o = 4; o; o >>= 1) {
            s += __shfl_xor_sync(0xffffffffu, s, o);
            q += __shfl_xor_sync(0xffffffffu, q, o);
        }
        if (lane == 0) { shs[0] = s; shq[0] = q; }
    }
    __syncthreads();
    s = shs[0]; q = shq[0];
    float mu  = s * (1.f/512.f);
    float var = q * (1.f/512.f) - mu*mu;
    float inv = rsqrtf(var + 1e-5f);
    float o0 = (a0 - mu) * inv * w[t]       + bb[t];
    float o1 = (a1 - mu) * inv * w[t + 256] + bb[t + 256];
    if (relu) { o0 = fmaxf(o0, 0.f); o1 = fmaxf(o1, 0.f); }
    out[base + t] = o0; out[base + t + 256] = o1;
}

// depthwise causal conv1d (k=4, pad left 3) on x half of g_xz, then SiLU -> g_xact
__global__ void k_dwconv(const float* __restrict__ w1, const float* __restrict__ b1) {
    int idx = blockIdx.x * blockDim.x + threadIdx.x;
    if (idx >= MROWS*DI) return;
    int c = idx & 1023;
    int m = idx >> 10;       // b*128 + l
    int l = m & 127;
    float acc = b1[c];
    #pragma unroll
    for (int k = 0; k < 4; k++) {
        int ls = l + k - 3;
        if (ls >= 0) acc += w1[c*4 + k] * g_xz[(size_t)(m + k - 3) * (2*DI) + c];
    }
    g_xact[idx] = acc / (1.f + __expf(-acc));   // silu
}

// selective scan. block = 256 d-channels for one batch b. B/C for the whole
// sequence live in smem (16KB), so the l-loop has no barriers.
// Fuses D-skip and silu(z) gating -> g_ys.
__global__ __launch_bounds__(256) void k_scan(const float* __restrict__ A_log,
                                              const float* __restrict__ D_skip)
{
    __shared__ float sB[LLEN][DS];
    __shared__ float sC[LLEN][DS];
    int b = blockIdx.y;
    int d = blockIdx.x * 256 + threadIdx.x;
    for (int i = threadIdx.x; i < LLEN*DS; i += 256) {
        int l = i >> 4, n = i & 15;
        sB[l][n] = g_dbc[(size_t)((b<<7)+l)*64 + 32 + n];
        sC[l][n] = g_dbc[(size_t)((b<<7)+l)*64 + 48 + n];
    }
    __syncthreads();
    float Ad[DS];
    #pragma unroll
    for (int n = 0; n < DS; n++) Ad[n] = -__expf(A_log[d*DS + n]);
    float Dv = D_skip[d];
    float h[DS];
    #pragma unroll
    for (int n = 0; n < DS; n++) h[n] = 0.f;
    for (int l = 0; l < LLEN; l++) {
        size_t off = (size_t)(b<<7) + l;
        float dtv = g_dt  [off*DI + d];
        float xv  = g_xact[off*DI + d];
        float zv  = g_xz  [off*(2*DI) + DI + d];
        float dx = dtv * xv;
        float acc = 0.f;
        #pragma unroll
        for (int n = 0; n < DS; n++) {
            h[n] = __expf(dtv * Ad[n]) * h[n] + dx * sB[l][n];
            acc += h[n] * sC[l][n];
        }
        float yv = acc + xv * Dv;
        float sz = zv / (1.f + __expf(-zv));
        g_ys[off*DI + d] = yv * sz;
    }
}

// coff[b,l] = dot(fts2[b,l,:], mlp_a_w) + mlp_a_b
__global__ void k_coff(const float* __restrict__ aw, const float* __restrict__ ab) {
    int row = blockIdx.x, t = threadIdx.x;   // 128 threads
    const float* xp = g_fts2 + (size_t)row * CDIM;
    float s = 0.f;
    #pragma unroll
    for (int i = 0; i < 4; i++) s += xp[t + i*128] * aw[t + i*128];
    __shared__ float sh[4];
    int lane = t & 31, wid = t >> 5;
    #pragma unroll
    for (int o = 16; o; o >>= 1) s += __shfl_xor_sync(0xffffffffu, s, o);
    if (lane == 0) sh[wid] = s;
    __syncthreads();
    if (t == 0) g_coff[row] = sh[0] + sh[1] + sh[2] + sh[3] + ab[0];
}

// out[b] = sigmoid(dot(coff[b,:], mlp_b_w) + mlp_b_b)
__global__ void k_out(const float* __restrict__ bw, const float* __restrict__ bbias,
                      float* __restrict__ out) {
    int b = blockIdx.x, t = threadIdx.x;     // 128 threads
    float s = g_coff[b*128 + t] * bw[t];
    __shared__ float sh[4];
    int lane = t & 31, wid = t >> 5;
    #pragma unroll
    for (int o = 16; o; o >>= 1) s += __shfl_xor_sync(0xffffffffu, s, o);
    if (lane == 0) sh[wid] = s;
    __syncthreads();
    if (t == 0) {
        float v = sh[0] + sh[1] + sh[2] + sh[3] + bbias[0];
        out[b] = 1.f / (1.f + __expf(-v));
    }
}

// ---------------- generic fp32 GEMM: C[M,N] = A[M,K] * B[N,K]^T (+bias)(+act) --
// act: 0 = none, 1 = softplus
#define GBM 128
#define GBN 128
#define GBK 8
#define GTM 8
#define GTN 8

__global__ __launch_bounds__(256) void sgemm_nt(
    int M, int N, int K,
    const float* __restrict__ A, int lda,
    const float* __restrict__ B, int ldb,
    float* __restrict__ C, int ldc,
    const float* __restrict__ bias, int act)
{
    __shared__ float As[GBK][GBM];
    __shared__ float Bs[GBK][GBN];
    const int tid  = threadIdx.x;
    const int bx   = blockIdx.x, by = blockIdx.y;
    const int tcol = tid % 16;
    const int trow = tid / 16;
    const int aRow = tid >> 1;        // 0..127
    const int aCol = (tid & 1) << 2;  // 0 or 4

    float acc[GTM][GTN];
    #pragma unroll
    for (int i = 0; i < GTM; i++)
        #pragma unroll
        for (int j = 0; j < GTN; j++) acc[i][j] = 0.f;

    const float* Abase = A + (size_t)(by*GBM + aRow) * lda + aCol;
    const int nIdx = bx*GBN + aRow;
    const float* Bbase = B + (size_t)nIdx * ldb + aCol;
    const bool bOK = (nIdx < N);

    for (int k0 = 0; k0 < K; k0 += GBK) {
        float4 av = *(const float4*)(Abase + k0);
        float4 bv = bOK ? *(const float4*)(Bbase + k0) : make_float4(0.f,0.f,0.f,0.f);
        As[aCol+0][aRow] = av.x; As[aCol+1][aRow] = av.y;
        As[aCol+2][aRow] = av.z; As[aCol+3][aRow] = av.w;
        Bs[aCol+0][aRow] = bv.x; Bs[aCol+1][aRow] = bv.y;
        Bs[aCol+2][aRow] = bv.z; Bs[aCol+3][aRow] = bv.w;
        __syncthreads();
        #pragma unroll
        for (int k = 0; k < GBK; k++) {
            float ar[GTM], br[GTN];
            #pragma unroll
            for (int i = 0; i < GTM; i++) ar[i] = As[k][trow*GTM + i];
            #pragma unroll
            for (int j = 0; j < GTN; j++) br[j] = Bs[k][tcol*GTN + j];
            #pragma unroll
            for (int i = 0; i < GTM; i++)
                #pragma unroll
                for (int j = 0; j < GTN; j++)
                    acc[i][j] += ar[i] * br[j];
        }
        __syncthreads();
    }
    #pragma unroll
    for (int i = 0; i < GTM; i++) {
        int row = by*GBM + trow*GTM + i;
        #pragma unroll
        for (int j = 0; j < GTN; j++) {
            int col = bx*GBN + tcol*GTN + j;
            if (col < N) {
                float v = acc[i][j];
                if (bias) v += bias[col];
                if (act == 1) v = (v > 20.f) ? v : log1pf(__expf(v));
                C[(size_t)row*ldc + col] = v;
            }
        }
    }
}

// ---------------- host ----------------
static float* sym(const void* s) {
    void* p = nullptr;
    cudaGetSymbolAddress(&p, s);
    return (float*)p;
}

extern "C" void kernel_launch(void* const* d_in, const int* in_sizes, int n_in,
                              void* d_out, int out_size) {
    const float* spt       = (const float*)d_in[0];
    const float* qry       = (const float*)d_in[1];
    const float* conv_w    = (const float*)d_in[2];
    const float* conv_b    = (const float*)d_in[3];
    const float* ln_w      = (const float*)d_in[4];
    const float* ln_b      = (const float*)d_in[5];
    const float* in_proj_w = (const float*)d_in[6];
    const float* conv1d_w  = (const float*)d_in[7];
    const float* conv1d_b  = (const float*)d_in[8];
    const float* x_proj_w  = (const float*)d_in[9];
    const float* dt_proj_w = (const float*)d_in[10];
    const float* dt_proj_b = (const float*)d_in[11];
    const float* A_log     = (const float*)d_in[12];
    const float* D_skip    = (const float*)d_in[13];
    const float* out_proj_w= (const float*)d_in[14];
    const float* mlp_a_w   = (const float*)d_in[15];
    const float* mlp_a_b   = (const float*)d_in[16];
    const float* mlp_b_w   = (const float*)d_in[17];
    const float* mlp_b_b   = (const float*)d_in[18];
    float* out = (float*)d_out;

    float* p_xcat = sym(g_xcat);
    float* p_wcat = sym(g_wcat);
    float* p_conv = sym(g_conv);
    float* p_F    = sym(g_F);
    float* p_xz   = sym(g_xz);
    float* p_xact = sym(g_xact);
    float* p_dbc  = sym(g_dbc);
    float* p_dt   = sym(g_dt);
    float* p_ys   = sym(g_ys);
    float* p_m    = sym(g_m);
    float* p_fts2 = sym(g_fts2);

    // 1. concat/reshape inputs -> fts0 (b,l,d)
    k_concat<<<(MROWS*CDIM + 255)/256, 256>>>(spt, qry);
    // 2. repack conv weights
    k_wcat<<<(CDIM*KCAT + 255)/256, 256>>>(conv_w);
    // 3. im2col
    k_im2col<<<(MROWS*KCAT + 255)/256, 256>>>();
    // 4. dense conv as GEMM: (8192,1536)x(512,1536)^T
    sgemm_nt<<<dim3((CDIM+GBN-1)/GBN, MROWS/GBM), 256>>>(
        MROWS, CDIM, KCAT, p_xcat, KCAT, p_wcat, KCAT, p_conv, CDIM, conv_b, 0);
    // 5. LN + relu -> F
    k_ln<<<MROWS, 256>>>(p_conv, nullptr, ln_w, ln_b, p_F, 1);
    // 6. in_proj: (8192,512)x(2048,512)^T -> xz
    sgemm_nt<<<dim3((2*DI)/GBN, MROWS/GBM), 256>>>(
        MROWS, 2*DI, CDIM, p_F, CDIM, in_proj_w, CDIM, p_xz, 2*DI, nullptr, 0);
    // 7. depthwise causal conv + silu -> xact
    k_dwconv<<<(MROWS*DI + 255)/256, 256>>>(conv1d_w, conv1d_b);
    // 8. x_proj: (8192,1024)x(64,1024)^T -> dbc
    sgemm_nt<<<dim3(1, MROWS/GBM), 256>>>(
        MROWS, 64, DI, p_xact, DI, x_proj_w, DI, p_dbc, 64, nullptr, 0);
    // 9. dt_proj + softplus: (8192,32)x(1024,32)^T -> dt
    sgemm_nt<<<dim3(DI/GBN, MROWS/GBM), 256>>>(
        MROWS, DI, DTR, p_dbc, 64, dt_proj_w, DTR, p_dt, DI, dt_proj_b, 1);
    // 10. selective scan (+D skip, +silu(z) gate) -> ys
    k_scan<<<dim3(DI/256, BB), 256>>>(A_log, D_skip);
    // 11. out_proj: (8192,1024)x(512,1024)^T -> m
    sgemm_nt<<<dim3(CDIM/GBN, MROWS/GBM), 256>>>(
        MROWS, CDIM, DI, p_ys, DI, out_proj_w, DI, p_m, CDIM, nullptr, 0);
    // 12. residual + LN -> fts2
    k_ln<<<MROWS, 256>>>(p_m, p_F, ln_w, ln_b, p_fts2, 0);
    // 13/14. MLP head -> sigmoid
    k_coff<<<MROWS, 128>>>(mlp_a_w, mlp_a_b);
    k_out<<<BB, 128>>>(mlp_b_w, mlp_b_b, out);
}

// round 5
// speedup vs baseline: 1.9121x; 1.9121x over previous
#include <cuda_runtime.h>
#include <math.h>

#define BB   64
#define LLEN 128
#define CDIM 512
#define DI   1024
#define DS   16
#define DTR  32
#define MROWS (BB*LLEN)   // 8192
#define KCAT  (CDIM*3)    // 1536

// ---------------- scratch (module-load allocated, allowed) ----------------
__device__ float g_fts0[MROWS*CDIM];
__device__ float g_wcat[CDIM*KCAT];
__device__ float g_conv[MROWS*CDIM];
__device__ float g_F   [MROWS*CDIM];
__device__ float g_xz  [MROWS*2*DI];
__device__ float g_xact[MROWS*DI];
__device__ float g_dbc [MROWS*64];
__device__ float g_dt  [MROWS*DI];
__device__ float g_ys  [MROWS*DI];
__device__ float g_m   [MROWS*CDIM];
__device__ float g_fts2[MROWS*CDIM];
__device__ float g_coff[MROWS];

// ---------------- elementwise / prep kernels ----------------

__global__ void k_concat(const float* __restrict__ spt, const float* __restrict__ qry) {
    int idx = blockIdx.x * blockDim.x + threadIdx.x;
    if (idx >= MROWS*CDIM) return;
    int b = idx >> 16;
    int r = idx & 65535;
    g_fts0[idx] = (r < 32768) ? spt[b*32768 + r] : qry[b*32768 + (r - 32768)];
}

// Wcat[o, k*512+i] = conv_w[o, i, k]
__global__ void k_wcat(const float* __restrict__ cw) {
    int idx = blockIdx.x * blockDim.x + threadIdx.x;
    if (idx >= CDIM*KCAT) return;
    int o = idx / KCAT, kk = idx % KCAT;
    int k = kk >> 9, i = kk & 511;
    g_wcat[idx] = cw[o*KCAT + i*3 + k];
}

// LayerNorm over 512 channels; optional residual; optional relu.
__global__ __launch_bounds__(256) void k_ln(const float* __restrict__ x,
                                            const float* __restrict__ res,
                                            const float* __restrict__ w,
                                            const float* __restrict__ bb,
                                            float* __restrict__ out, int relu)
{
    int row = blockIdx.x;
    size_t base = (size_t)row * CDIM;
    int t = threadIdx.x;
    float a0 = x[base + t], a1 = x[base + t + 256];
    if (res) { a0 += res[base + t]; a1 += res[base + t + 256]; }
    float s = a0 + a1, q = a0*a0 + a1*a1;
    __shared__ float shs[8], shq[8];
    int lane = t & 31, wid = t >> 5;
    #pragma unroll
    for (int o = 16; o; o >>= 1) {
        s += __shfl_xor_sync(0xffffffffu, s, o);
        q += __shfl_xor_sync(0xffffffffu, q, o);
    }
    if (lane == 0) { shs[wid] = s; shq[wid] = q; }
    __syncthreads();
    if (t < 32) {
        s = (lane < 8) ? shs[lane] : 0.f;
        q = (lane < 8) ? shq[lane] : 0.f;
        #pragma unroll
        for (int o = 4; o; o >>= 1) {
            s += __shfl_xor_sync(0xffffffffu, s, o);
            q += __shfl_xor_sync(0xffffffffu, q, o);
        }
        if (lane == 0) { shs[0] = s; shq[0] = q; }
    }
    __syncthreads();
    s = shs[0]; q = shq[0];
    float mu  = s * (1.f/512.f);
    float var = q * (1.f/512.f) - mu*mu;
    float inv = rsqrtf(var + 1e-5f);
    float o0 = (a0 - mu) * inv * w[t]       + bb[t];
    float o1 = (a1 - mu) * inv * w[t + 256] + bb[t + 256];
    if (relu) { o0 = fmaxf(o0, 0.f); o1 = fmaxf(o1, 0.f); }
    out[base + t] = o0; out[base + t + 256] = o1;
}

// depthwise causal conv1d (k=4, pad left 3) on x half of g_xz, then SiLU
__global__ void k_dwconv(const float* __restrict__ w1, const float* __restrict__ b1) {
    int idx = blockIdx.x * blockDim.x + threadIdx.x;
    if (idx >= MROWS*DI) return;
    int c = idx & 1023;
    int m = idx >> 10;
    int l = m & 127;
    float acc = b1[c];
    #pragma unroll
    for (int k = 0; k < 4; k++) {
        int ls = l + k - 3;
        if (ls >= 0) acc += w1[c*4 + k] * g_xz[(size_t)(m + k - 3) * (2*DI) + c];
    }
    g_xact[idx] = acc / (1.f + __expf(-acc));
}

// selective scan (+D skip, +silu(z) gate)
__global__ __launch_bounds__(256) void k_scan(const float* __restrict__ A_log,
                                              const float* __restrict__ D_skip)
{
    __shared__ float sB[LLEN][DS];
    __shared__ float sC[LLEN][DS];
    int b = blockIdx.y;
    int d = blockIdx.x * 256 + threadIdx.x;
    for (int i = threadIdx.x; i < LLEN*DS; i += 256) {
        int l = i >> 4, n = i & 15;
        sB[l][n] = g_dbc[(size_t)((b<<7)+l)*64 + 32 + n];
        sC[l][n] = g_dbc[(size_t)((b<<7)+l)*64 + 48 + n];
    }
    __syncthreads();
    float Ad[DS];
    #pragma unroll
    for (int n = 0; n < DS; n++) Ad[n] = -__expf(A_log[d*DS + n]);
    float Dv = D_skip[d];
    float h[DS];
    #pragma unroll
    for (int n = 0; n < DS; n++) h[n] = 0.f;
    for (int l = 0; l < LLEN; l++) {
        size_t off = (size_t)(b<<7) + l;
        float dtv = g_dt  [off*DI + d];
        float xv  = g_xact[off*DI + d];
        float zv  = g_xz  [off*(2*DI) + DI + d];
        float dx = dtv * xv;
        float acc = 0.f;
        #pragma unroll
        for (int n = 0; n < DS; n++) {
            h[n] = __expf(dtv * Ad[n]) * h[n] + dx * sB[l][n];
            acc += h[n] * sC[l][n];
        }
        float yv = acc + xv * Dv;
        float sz = zv / (1.f + __expf(-zv));
        g_ys[off*DI + d] = yv * sz;
    }
}

__global__ void k_coff(const float* __restrict__ aw, const float* __restrict__ ab) {
    int row = blockIdx.x, t = threadIdx.x;
    const float* xp = g_fts2 + (size_t)row * CDIM;
    float s = 0.f;
    #pragma unroll
    for (int i = 0; i < 4; i++) s += xp[t + i*128] * aw[t + i*128];
    __shared__ float sh[4];
    int lane = t & 31, wid = t >> 5;
    #pragma unroll
    for (int o = 16; o; o >>= 1) s += __shfl_xor_sync(0xffffffffu, s, o);
    if (lane == 0) sh[wid] = s;
    __syncthreads();
    if (t == 0) g_coff[row] = sh[0] + sh[1] + sh[2] + sh[3] + ab[0];
}

__global__ void k_out(const float* __restrict__ bw, const float* __restrict__ bbias,
                      float* __restrict__ out) {
    int b = blockIdx.x, t = threadIdx.x;
    float s = g_coff[b*128 + t] * bw[t];
    __shared__ float sh[4];
    int lane = t & 31, wid = t >> 5;
    #pragma unroll
    for (int o = 16; o; o >>= 1) s += __shfl_xor_sync(0xffffffffu, s, o);
    if (lane == 0) sh[wid] = s;
    __syncthreads();
    if (t == 0) {
        float v = sh[0] + sh[1] + sh[2] + sh[3] + bbias[0];
        out[b] = 1.f / (1.f + __expf(-v));
    }
}

// ================= TF32 tensor-core GEMM: C[M,N] = A[M,K] * B[N,K]^T =========
// 128x128 block tile, BK=16, double-buffered smem, 8 warps (4m x 2n),
// warp tile 32x64, mma.m16n8k8.tf32. N, M multiples of 128; K multiple of 16.
// convMode=1: A is g_fts0 [b*128+l, 512]; logical A[(b,l), s*512+i] =
//             fts0[b, l+s-1, i] (zero outside) -> fused im2col.

__device__ __forceinline__ unsigned f2tf32(float f) {
    unsigned u;
    asm("cvt.rna.tf32.f32 %0, %1;" : "=r"(u) : "f"(f));
    return u;
}

#define TBM 128
#define TBN 128
#define TBK 16
#define TLD 20   // padded row stride (conflict-free frag reads)

__global__ __launch_bounds__(256) void gemm_tf32(
    int M, int N, int K,
    const float* __restrict__ A, int lda,
    const float* __restrict__ B, int ldb,
    float* __restrict__ C, int ldc,
    const float* __restrict__ bias, int convMode)
{
    __shared__ unsigned As[2][TBM*TLD];
    __shared__ unsigned Bs[2][TBN*TLD];

    const int tid  = threadIdx.x;
    const int lane = tid & 31;
    const int wid  = tid >> 5;
    const int wm   = wid & 3;       // 0..3 -> m offset wm*32
    const int wn   = wid >> 2;      // 0..1 -> n offset wn*64
    const int bx = blockIdx.x, by = blockIdx.y;

    float acc[2][8][4];
    #pragma unroll
    for (int i = 0; i < 2; i++)
        #pragma unroll
        for (int j = 0; j < 8; j++)
            #pragma unroll
            for (int v = 0; v < 4; v++) acc[i][j][v] = 0.f;

    // loader lambdas -------------------------------------------------------
    auto loadA = [&](int kt, float4 av[2]) {
        int k0 = kt * TBK;
        #pragma unroll
        for (int i = 0; i < 2; i++) {
            int p   = tid + i*256;       // 0..511
            int row = p >> 2;            // 0..127
            int kq  = (p & 3) << 2;      // 0,4,8,12
            if (!convMode) {
                av[i] = *(const float4*)(A + (size_t)(by*TBM + row)*lda + k0 + kq);
            } else {
                int m  = by*TBM + row;
                int l  = m & 127;
                int s  = k0 >> 9;        // shift 0..2 (fixed within tile)
                int lp = l + s - 1;
                if ((unsigned)lp < 128u)
                    av[i] = *(const float4*)(A + (size_t)((m & ~127) + lp)*512
                                               + (k0 & 511) + kq);
                else
                    av[i] = make_float4(0.f, 0.f, 0.f, 0.f);
            }
        }
    };
    auto loadB = [&](int kt, float4 bv[2]) {
        int k0 = kt * TBK;
        #pragma unroll
        for (int i = 0; i < 2; i++) {
            int p   = tid + i*256;
            int row = p >> 2;
            int kq  = (p & 3) << 2;
            bv[i] = *(const float4*)(B + (size_t)(bx*TBN + row)*ldb + k0 + kq);
        }
    };
    auto stage = [&](int buf, const float4 av[2], const float4 bv[2]) {
        #pragma unroll
        for (int i = 0; i < 2; i++) {
            int p   = tid + i*256;
            int row = p >> 2;
            int kq  = (p & 3) << 2;
            uint4 ua = make_uint4(f2tf32(av[i].x), f2tf32(av[i].y),
                                  f2tf32(av[i].z), f2tf32(av[i].w));
            uint4 ub = make_uint4(f2tf32(bv[i].x), f2tf32(bv[i].y),
                                  f2tf32(bv[i].z), f2tf32(bv[i].w));
            *(uint4*)&As[buf][row*TLD + kq] = ua;
            *(uint4*)&Bs[buf][row*TLD + kq] = ub;
        }
    };

    float4 avr[2], bvr[2];
    loadA(0, avr); loadB(0, bvr);
    stage(0, avr, bvr);
    __syncthreads();

    const int KT = K / TBK;
    for (int kt = 0; kt < KT; kt++) {
        int cur = kt & 1;
        if (kt + 1 < KT) { loadA(kt+1, avr); loadB(kt+1, bvr); }

        #pragma unroll
        for (int ks = 0; ks < 2; ks++) {
            int kb = ks * 8;
            unsigned af[2][4], bf[8][2];
            #pragma unroll
            for (int mt = 0; mt < 2; mt++) {
                int r0 = wm*32 + mt*16 + (lane >> 2);
                af[mt][0] = As[cur][ r0     *TLD + kb + (lane & 3)    ];
                af[mt][1] = As[cur][(r0 + 8)*TLD + kb + (lane & 3)    ];
                af[mt][2] = As[cur][ r0     *TLD + kb + (lane & 3) + 4];
                af[mt][3] = As[cur][(r0 + 8)*TLD + kb + (lane & 3) + 4];
            }
            #pragma unroll
            for (int nt = 0; nt < 8; nt++) {
                int c0 = wn*64 + nt*8 + (lane >> 2);
                bf[nt][0] = Bs[cur][c0*TLD + kb + (lane & 3)    ];
                bf[nt][1] = Bs[cur][c0*TLD + kb + (lane & 3) + 4];
            }
            #pragma unroll
            for (int mt = 0; mt < 2; mt++)
                #pragma unroll
                for (int nt = 0; nt < 8; nt++) {
                    asm volatile(
                        "mma.sync.aligned.m16n8k8.row.col.f32.tf32.tf32.f32 "
                        "{%0,%1,%2,%3},{%4,%5,%6,%7},{%8,%9},{%0,%1,%2,%3};"
                        : "+f"(acc[mt][nt][0]), "+f"(acc[mt][nt][1]),
                          "+f"(acc[mt][nt][2]), "+f"(acc[mt][nt][3])
                        : "r"(af[mt][0]), "r"(af[mt][1]),
                          "r"(af[mt][2]), "r"(af[mt][3]),
                          "r"(bf[nt][0]), "r"(bf[nt][1]));
                }
        }

        if (kt + 1 < KT) {
            stage(cur ^ 1, avr, bvr);
            __syncthreads();
        }
    }

    // epilogue -------------------------------------------------------------
    #pragma unroll
    for (int mt = 0; mt < 2; mt++) {
        int r0 = by*TBM + wm*32 + mt*16 + (lane >> 2);
        #pragma unroll
        for (int nt = 0; nt < 8; nt++) {
            int c = bx*TBN + wn*64 + nt*8 + 2*(lane & 3);
            float bb0 = bias ? bias[c]   : 0.f;
            float bb1 = bias ? bias[c+1] : 0.f;
            float2 v0 = make_float2(acc[mt][nt][0] + bb0, acc[mt][nt][1] + bb1);
            float2 v1 = make_float2(acc[mt][nt][2] + bb0, acc[mt][nt][3] + bb1);
            *(float2*)(C + (size_t) r0     *ldc + c) = v0;
            *(float2*)(C + (size_t)(r0 + 8)*ldc + c) = v1;
        }
    }
}

// ---------------- fp32 fallback GEMM (small N / K GEMMs) ---------------------
#define GBM 128
#define GBN 128
#define GBK 8
#define GTM 8
#define GTN 8

__global__ __launch_bounds__(256) void sgemm_nt(
    int M, int N, int K,
    const float* __restrict__ A, int lda,
    const float* __restrict__ B, int ldb,
    float* __restrict__ C, int ldc,
    const float* __restrict__ bias, int act)
{
    __shared__ float As[GBK][GBM];
    __shared__ float Bs[GBK][GBN];
    const int tid  = threadIdx.x;
    const int bx   = blockIdx.x, by = blockIdx.y;
    const int tcol = tid % 16;
    const int trow = tid / 16;
    const int aRow = tid >> 1;
    const int aCol = (tid & 1) << 2;

    float acc[GTM][GTN];
    #pragma unroll
    for (int i = 0; i < GTM; i++)
        #pragma unroll
        for (int j = 0; j < GTN; j++) acc[i][j] = 0.f;

    const float* Abase = A + (size_t)(by*GBM + aRow) * lda + aCol;
    const int nIdx = bx*GBN + aRow;
    const float* Bbase = B + (size_t)nIdx * ldb + aCol;
    const bool bOK = (nIdx < N);

    for (int k0 = 0; k0 < K; k0 += GBK) {
        float4 av = *(const float4*)(Abase + k0);
        float4 bv = bOK ? *(const float4*)(Bbase + k0) : make_float4(0.f,0.f,0.f,0.f);
        As[aCol+0][aRow] = av.x; As[aCol+1][aRow] = av.y;
        As[aCol+2][aRow] = av.z; As[aCol+3][aRow] = av.w;
        Bs[aCol+0][aRow] = bv.x; Bs[aCol+1][aRow] = bv.y;
        Bs[aCol+2][aRow] = bv.z; Bs[aCol+3][aRow] = bv.w;
        __syncthreads();
        #pragma unroll
        for (int k = 0; k < GBK; k++) {
            float ar[GTM], br[GTN];
            #pragma unroll
            for (int i = 0; i < GTM; i++) ar[i] = As[k][trow*GTM + i];
            #pragma unroll
            for (int j = 0; j < GTN; j++) br[j] = Bs[k][tcol*GTN + j];
            #pragma unroll
            for (int i = 0; i < GTM; i++)
                #pragma unroll
                for (int j = 0; j < GTN; j++)
                    acc[i][j] += ar[i] * br[j];
        }
        __syncthreads();
    }
    #pragma unroll
    for (int i = 0; i < GTM; i++) {
        int row = by*GBM + trow*GTM + i;
        #pragma unroll
        for (int j = 0; j < GTN; j++) {
            int col = bx*GBN + tcol*GTN + j;
            if (col < N) {
                float v = acc[i][j];
                if (bias) v += bias[col];
                if (act == 1) v = (v > 20.f) ? v : log1pf(__expf(v));
                C[(size_t)row*ldc + col] = v;
            }
        }
    }
}

// ---------------- host ----------------
static float* sym(const void* s) {
    void* p = nullptr;
    cudaGetSymbolAddress(&p, s);
    return (float*)p;
}

extern "C" void kernel_launch(void* const* d_in, const int* in_sizes, int n_in,
                              void* d_out, int out_size) {
    const float* spt       = (const float*)d_in[0];
    const float* qry       = (const float*)d_in[1];
    const float* conv_w    = (const float*)d_in[2];
    const float* conv_b    = (const float*)d_in[3];
    const float* ln_w      = (const float*)d_in[4];
    const float* ln_b      = (const float*)d_in[5];
    const float* in_proj_w = (const float*)d_in[6];
    const float* conv1d_w  = (const float*)d_in[7];
    const float* conv1d_b  = (const float*)d_in[8];
    const float* x_proj_w  = (const float*)d_in[9];
    const float* dt_proj_w = (const float*)d_in[10];
    const float* dt_proj_b = (const float*)d_in[11];
    const float* A_log     = (const float*)d_in[12];
    const float* D_skip    = (const float*)d_in[13];
    const float* out_proj_w= (const float*)d_in[14];
    const float* mlp_a_w   = (const float*)d_in[15];
    const float* mlp_a_b   = (const float*)d_in[16];
    const float* mlp_b_w   = (const float*)d_in[17];
    const float* mlp_b_b   = (const float*)d_in[18];
    float* out = (float*)d_out;

    float* p_fts0 = sym(g_fts0);
    float* p_wcat = sym(g_wcat);
    float* p_conv = sym(g_conv);
    float* p_F    = sym(g_F);
    float* p_xz   = sym(g_xz);
    float* p_xact = sym(g_xact);
    float* p_dbc  = sym(g_dbc);
    float* p_dt   = sym(g_dt);
    float* p_ys   = sym(g_ys);
    float* p_m    = sym(g_m);
    float* p_fts2 = sym(g_fts2);

    // 1. concat/reshape inputs -> fts0 (b,l,d)
    k_concat<<<(MROWS*CDIM + 255)/256, 256>>>(spt, qry);
    // 2. repack conv weights
    k_wcat<<<(CDIM*KCAT + 255)/256, 256>>>(conv_w);
    // 3. dense conv as tf32 GEMM with fused im2col: (8192,1536)x(512,1536)^T
    gemm_tf32<<<dim3(CDIM/TBN, MROWS/TBM), 256>>>(
        MROWS, CDIM, KCAT, p_fts0, 512, p_wcat, KCAT, p_conv, CDIM, conv_b, 1);
    // 4. LN + relu -> F
    k_ln<<<MROWS, 256>>>(p_conv, nullptr, ln_w, ln_b, p_F, 1);
    // 5. in_proj tf32: (8192,512)x(2048,512)^T -> xz
    gemm_tf32<<<dim3((2*DI)/TBN, MROWS/TBM), 256>>>(
        MROWS, 2*DI, CDIM, p_F, CDIM, in_proj_w, CDIM, p_xz, 2*DI, nullptr, 0);
    // 6. depthwise causal conv + silu -> xact
    k_dwconv<<<(MROWS*DI + 255)/256, 256>>>(conv1d_w, conv1d_b);
    // 7. x_proj fp32: (8192,1024)x(64,1024)^T -> dbc
    sgemm_nt<<<dim3(1, MROWS/GBM), 256>>>(
        MROWS, 64, DI, p_xact, DI, x_proj_w, DI, p_dbc, 64, nullptr, 0);
    // 8. dt_proj + softplus fp32: (8192,32)x(1024,32)^T -> dt
    sgemm_nt<<<dim3(DI/GBN, MROWS/GBM), 256>>>(
        MROWS, DI, DTR, p_dbc, 64, dt_proj_w, DTR, p_dt, DI, dt_proj_b, 1);
    // 9. selective scan -> ys
    k_scan<<<dim3(DI/256, BB), 256>>>(A_log, D_skip);
    // 10. out_proj tf32: (8192,1024)x(512,1024)^T -> m
    gemm_tf32<<<dim3(CDIM/TBN, MROWS/TBM), 256>>>(
        MROWS, CDIM, DI, p_ys, DI, out_proj_w, DI, p_m, CDIM, nullptr, 0);
    // 11. residual + LN -> fts2
    k_ln<<<MROWS, 256>>>(p_m, p_F, ln_w, ln_b, p_fts2, 0);
    // 12/13. MLP head -> sigmoid
    k_coff<<<MROWS, 128>>>(mlp_a_w, mlp_a_b);
    k_out<<<BB, 128>>>(mlp_b_w, mlp_b_b, out);
}

// round 7
// speedup vs baseline: 2.8302x; 1.4801x over previous
#include <cuda_runtime.h>
#include <cuda_bf16.h>
#include <math.h>

#define BB   64
#define LLEN 128
#define CDIM 512
#define DI   1024
#define DS   16
#define DTR  32
#define MROWS (BB*LLEN)   // 8192
#define KCAT  (CDIM*3)    // 1536

// ---------------- scratch ----------------
__device__ float g_fts0[MROWS*CDIM];
__device__ float g_wcat[CDIM*KCAT];
__device__ float g_conv[MROWS*CDIM];
__device__ float g_F   [MROWS*CDIM];
__device__ float g_xz  [MROWS*2*DI];
__device__ float g_xact[MROWS*DI];
__device__ float g_dbc [MROWS*64];
__device__ float g_dt  [MROWS*DI];
__device__ float g_ys  [MROWS*DI];
__device__ float g_m   [MROWS*CDIM];
__device__ float g_fts2[MROWS*CDIM];
__device__ float g_coff[MROWS];

// ---------------- elementwise / prep kernels ----------------

__global__ void k_concat(const float* __restrict__ spt, const float* __restrict__ qry) {
    int idx = blockIdx.x * blockDim.x + threadIdx.x;
    if (idx >= MROWS*CDIM) return;
    int b = idx >> 16;
    int r = idx & 65535;
    g_fts0[idx] = (r < 32768) ? spt[b*32768 + r] : qry[b*32768 + (r - 32768)];
}

// Wcat[o, k*512+i] = conv_w[o, i, k]
__global__ void k_wcat(const float* __restrict__ cw) {
    int idx = blockIdx.x * blockDim.x + threadIdx.x;
    if (idx >= CDIM*KCAT) return;
    int o = idx / KCAT, kk = idx % KCAT;
    int k = kk >> 9, i = kk & 511;
    g_wcat[idx] = cw[o*KCAT + i*3 + k];
}

// LayerNorm over 512 channels; optional residual; optional relu.
__global__ __launch_bounds__(256) void k_ln(const float* __restrict__ x,
                                            const float* __restrict__ res,
                                            const float* __restrict__ w,
                                            const float* __restrict__ bb,
                                            float* __restrict__ out, int relu)
{
    int row = blockIdx.x;
    size_t base = (size_t)row * CDIM;
    int t = threadIdx.x;
    float a0 = x[base + t], a1 = x[base + t + 256];
    if (res) { a0 += res[base + t]; a1 += res[base + t + 256]; }
    float s = a0 + a1, q = a0*a0 + a1*a1;
    __shared__ float shs[8], shq[8];
    int lane = t & 31, wid = t >> 5;
    #pragma unroll
    for (int o = 16; o; o >>= 1) {
        s += __shfl_xor_sync(0xffffffffu, s, o);
        q += __shfl_xor_sync(0xffffffffu, q, o);
    }
    if (lane == 0) { shs[wid] = s; shq[wid] = q; }
    __syncthreads();
    if (t < 32) {
        s = (lane < 8) ? shs[lane] : 0.f;
        q = (lane < 8) ? shq[lane] : 0.f;
        #pragma unroll
        for (int o = 4; o; o >>= 1) {
            s += __shfl_xor_sync(0xffffffffu, s, o);
            q += __shfl_xor_sync(0xffffffffu, q, o);
        }
        if (lane == 0) { shs[0] = s; shq[0] = q; }
    }
    __syncthreads();
    s = shs[0]; q = shq[0];
    float mu  = s * (1.f/512.f);
    float var = q * (1.f/512.f) - mu*mu;
    float inv = rsqrtf(var + 1e-5f);
    float o0 = (a0 - mu) * inv * w[t]       + bb[t];
    float o1 = (a1 - mu) * inv * w[t + 256] + bb[t + 256];
    if (relu) { o0 = fmaxf(o0, 0.f); o1 = fmaxf(o1, 0.f); }
    out[base + t] = o0; out[base + t + 256] = o1;
}

// depthwise causal conv1d (k=4, pad left 3) on x half of g_xz, then SiLU
__global__ void k_dwconv(const float* __restrict__ w1, const float* __restrict__ b1) {
    int idx = blockIdx.x * blockDim.x + threadIdx.x;
    if (idx >= MROWS*DI) return;
    int c = idx & 1023;
    int m = idx >> 10;
    int l = m & 127;
    float acc = b1[c];
    #pragma unroll
    for (int k = 0; k < 4; k++) {
        int ls = l + k - 3;
        if (ls >= 0) acc += w1[c*4 + k] * g_xz[(size_t)(m + k - 3) * (2*DI) + c];
    }
    g_xact[idx] = acc / (1.f + __expf(-acc));
}

// selective scan (+D skip, +silu(z) gate)
__global__ __launch_bounds__(256) void k_scan(const float* __restrict__ A_log,
                                              const float* __restrict__ D_skip)
{
    __shared__ float sB[LLEN][DS];
    __shared__ float sC[LLEN][DS];
    int b = blockIdx.y;
    int d = blockIdx.x * 256 + threadIdx.x;
    for (int i = threadIdx.x; i < LLEN*DS; i += 256) {
        int l = i >> 4, n = i & 15;
        sB[l][n] = g_dbc[(size_t)((b<<7)+l)*64 + 32 + n];
        sC[l][n] = g_dbc[(size_t)((b<<7)+l)*64 + 48 + n];
    }
    __syncthreads();
    float Ad[DS];
    #pragma unroll
    for (int n = 0; n < DS; n++) Ad[n] = -__expf(A_log[d*DS + n]);
    float Dv = D_skip[d];
    float h[DS];
    #pragma unroll
    for (int n = 0; n < DS; n++) h[n] = 0.f;
    for (int l = 0; l < LLEN; l++) {
        size_t off = (size_t)(b<<7) + l;
        float dtv = g_dt  [off*DI + d];
        float xv  = g_xact[off*DI + d];
        float zv  = g_xz  [off*(2*DI) + DI + d];
        float dx = dtv * xv;
        float acc = 0.f;
        #pragma unroll
        for (int n = 0; n < DS; n++) {
            h[n] = __expf(dtv * Ad[n]) * h[n] + dx * sB[l][n];
            acc += h[n] * sC[l][n];
        }
        float yv = acc + xv * Dv;
        float sz = zv / (1.f + __expf(-zv));
        g_ys[off*DI + d] = yv * sz;
    }
}

__global__ void k_coff(const float* __restrict__ aw, const float* __restrict__ ab) {
    int row = blockIdx.x, t = threadIdx.x;
    const float* xp = g_fts2 + (size_t)row * CDIM;
    float s = 0.f;
    #pragma unroll
    for (int i = 0; i < 4; i++) s += xp[t + i*128] * aw[t + i*128];
    __shared__ float sh[4];
    int lane = t & 31, wid = t >> 5;
    #pragma unroll
    for (int o = 16; o; o >>= 1) s += __shfl_xor_sync(0xffffffffu, s, o);
    if (lane == 0) sh[wid] = s;
    __syncthreads();
    if (t == 0) g_coff[row] = sh[0] + sh[1] + sh[2] + sh[3] + ab[0];
}

__global__ void k_out(const float* __restrict__ bw, const float* __restrict__ bbias,
                      float* __restrict__ out) {
    int b = blockIdx.x, t = threadIdx.x;
    float s = g_coff[b*128 + t] * bw[t];
    __shared__ float sh[4];
    int lane = t & 31, wid = t >> 5;
    #pragma unroll
    for (int o = 16; o; o >>= 1) s += __shfl_xor_sync(0xffffffffu, s, o);
    if (lane == 0) sh[wid] = s;
    __syncthreads();
    if (t == 0) {
        float v = sh[0] + sh[1] + sh[2] + sh[3] + bbias[0];
        out[b] = 1.f / (1.f + __expf(-v));
    }
}

// ================= BF16 tensor-core GEMM: C[M,N] = A[M,K] * B[N,K]^T =========
// fp32 in/out, bf16 compute. 128x128 tile, BK=32, double-buffered, 8 warps
// (4m x 2n), warp tile 32x64, mma.m16n8k16.bf16. M,N mult of 128; K mult of 32.
// convMode=1: fused im2col over g_fts0 (shift s = k0>>9 constant per k-tile).

#define TBM 128
#define TBN 128
#define TBK 32
#define HLD 20   // uints per smem row (16 data + 4 pad) -> conflict-free frags

__global__ __launch_bounds__(256) void gemm_bf16(
    int M, int N, int K,
    const float* __restrict__ A, int lda,
    const float* __restrict__ B, int ldb,
    float* __restrict__ C, int ldc,
    const float* __restrict__ bias, int convMode)
{
    __shared__ unsigned As[2][TBM*HLD];
    __shared__ unsigned Bs[2][TBN*HLD];

    const int tid  = threadIdx.x;
    const int lane = tid & 31;
    const int wid  = tid >> 5;
    const int wm   = wid & 3;
    const int wn   = wid >> 2;
    const int bx = blockIdx.x, by = blockIdx.y;

    float acc[2][8][4];
    #pragma unroll
    for (int i = 0; i < 2; i++)
        #pragma unroll
        for (int j = 0; j < 8; j++)
            #pragma unroll
            for (int v = 0; v < 4; v++) acc[i][j][v] = 0.f;

    auto loadA = [&](int kt, float4 av[4]) {
        int k0 = kt * TBK;
        #pragma unroll
        for (int i = 0; i < 4; i++) {
            int p   = tid + i*256;       // 0..1023
            int row = p >> 3;            // 0..127
            int kq  = (p & 7) << 2;      // 0..28 step 4
            if (!convMode) {
                av[i] = *(const float4*)(A + (size_t)(by*TBM + row)*lda + k0 + kq);
            } else {
                int m  = by*TBM + row;
                int l  = m & 127;
                int s  = k0 >> 9;        // shift constant within tile (512%32==0)
                int lp = l + s - 1;
                if ((unsigned)lp < 128u)
                    av[i] = *(const float4*)(A + (size_t)((m & ~127) + lp)*512
                                               + (k0 & 511) + kq);
                else
                    av[i] = make_float4(0.f, 0.f, 0.f, 0.f);
            }
        }
    };
    auto loadB = [&](int kt, float4 bv[4]) {
        int k0 = kt * TBK;
        #pragma unroll
        for (int i = 0; i < 4; i++) {
            int p   = tid + i*256;
            int row = p >> 3;
            int kq  = (p & 7) << 2;
            bv[i] = *(const float4*)(B + (size_t)(bx*TBN + row)*ldb + k0 + kq);
        }
    };
    auto stage = [&](int buf, const float4 av[4], const float4 bv[4]) {
        #pragma unroll
        for (int i = 0; i < 4; i++) {
            int p   = tid + i*256;
            int row = p >> 3;
            int kq2 = (p & 7) << 1;      // uint offset 0..14 step 2
            __nv_bfloat162 a0 = __float22bfloat162_rn(make_float2(av[i].x, av[i].y));
            __nv_bfloat162 a1 = __float22bfloat162_rn(make_float2(av[i].z, av[i].w));
            __nv_bfloat162 b0 = __float22bfloat162_rn(make_float2(bv[i].x, bv[i].y));
            __nv_bfloat162 b1 = __float22bfloat162_rn(make_float2(bv[i].z, bv[i].w));
            *(uint2*)&As[buf][row*HLD + kq2] =
                make_uint2(*(unsigned*)&a0, *(unsigned*)&a1);
            *(uint2*)&Bs[buf][row*HLD + kq2] =
                make_uint2(*(unsigned*)&b0, *(unsigned*)&b1);
        }
    };

    float4 avr[4], bvr[4];
    loadA(0, avr); loadB(0, bvr);
    stage(0, avr, bvr);
    __syncthreads();

    const int KT = K / TBK;
    for (int kt = 0; kt < KT; kt++) {
        int cur = kt & 1;
        if (kt + 1 < KT) { loadA(kt+1, avr); loadB(kt+1, bvr); }

        #pragma unroll
        for (int ks = 0; ks < 2; ks++) {
            int kb = ks * 8;             // uint offset of 16-k chunk
            unsigned af[2][4], bf[8][2];
            #pragma unroll
            for (int mt = 0; mt < 2; mt++) {
                int r0 = wm*32 + mt*16 + (lane >> 2);
                af[mt][0] = As[cur][ r0     *HLD + kb + (lane & 3)    ];
                af[mt][1] = As[cur][(r0 + 8)*HLD + kb + (lane & 3)    ];
                af[mt][2] = As[cur][ r0     *HLD + kb + (lane & 3) + 4];
                af[mt][3] = As[cur][(r0 + 8)*HLD + kb + (lane & 3) + 4];
            }
            #pragma unroll
            for (int nt = 0; nt < 8; nt++) {
                int c0 = wn*64 + nt*8 + (lane >> 2);
                bf[nt][0] = Bs[cur][c0*HLD + kb + (lane & 3)    ];
                bf[nt][1] = Bs[cur][c0*HLD + kb + (lane & 3) + 4];
            }
            #pragma unroll
            for (int mt = 0; mt < 2; mt++)
                #pragma unroll
                for (int nt = 0; nt < 8; nt++) {
                    asm volatile(
                        "mma.sync.aligned.m16n8k16.row.col.f32.bf16.bf16.f32 "
                        "{%0,%1,%2,%3},{%4,%5,%6,%7},{%8,%9},{%0,%1,%2,%3};"
                        : "+f"(acc[mt][nt][0]), "+f"(acc[mt][nt][1]),
                          "+f"(acc[mt][nt][2]), "+f"(acc[mt][nt][3])
                        : "r"(af[mt][0]), "r"(af[mt][1]),
                          "r"(af[mt][2]), "r"(af[mt][3]),
                          "r"(bf[nt][0]), "r"(bf[nt][1]));
                }
        }

        if (kt + 1 < KT) {
            stage(cur ^ 1, avr, bvr);
            __syncthreads();
        }
    }

    #pragma unroll
    for (int mt = 0; mt < 2; mt++) {
        int r0 = by*TBM + wm*32 + mt*16 + (lane >> 2);
        #pragma unroll
        for (int nt = 0; nt < 8; nt++) {
            int c = bx*TBN + wn*64 + nt*8 + 2*(lane & 3);
            float bb0 = bias ? bias[c]   : 0.f;
            float bb1 = bias ? bias[c+1] : 0.f;
            float2 v0 = make_float2(acc[mt][nt][0] + bb0, acc[mt][nt][1] + bb1);
            float2 v1 = make_float2(acc[mt][nt][2] + bb0, acc[mt][nt][3] + bb1);
            *(float2*)(C + (size_t) r0     *ldc + c) = v0;
            *(float2*)(C + (size_t)(r0 + 8)*ldc + c) = v1;
        }
    }
}

// ---------------- fp32 64x64-tile GEMM (x_proj: M=8192, N=64, K=1024) -------
// grid (1, M/64), 256 threads, thread tile 4x4.
__global__ __launch_bounds__(256) void sgemm64(
    int M, int K,
    const float* __restrict__ A, int lda,   // [M,K]
    const float* __restrict__ B, int ldb,   // [64,K]
    float* __restrict__ C)                  // [M,64]
{
    __shared__ float As[64][10];  // [row][k] padded
    __shared__ float Bs[64][10];
    const int tid  = threadIdx.x;
    const int by   = blockIdx.y;
    const int trow = tid >> 4;        // 0..15
    const int tcol = tid & 15;        // 0..15
    const int aRow = tid >> 2;        // 0..63
    const int aCol = (tid & 3) << 1;  // 0,2,4,6

    float acc[4][4];
    #pragma unroll
    for (int i = 0; i < 4; i++)
        #pragma unroll
        for (int j = 0; j < 4; j++) acc[i][j] = 0.f;

    const float* Ab = A + (size_t)(by*64 + aRow)*lda + aCol;
    const float* Bb = B + (size_t)aRow*ldb + aCol;

    for (int k0 = 0; k0 < K; k0 += 8) {
        float2 av = *(const float2*)(Ab + k0);
        float2 bv = *(const float2*)(Bb + k0);
        As[aRow][aCol] = av.x; As[aRow][aCol+1] = av.y;
        Bs[aRow][aCol] = bv.x; Bs[aRow][aCol+1] = bv.y;
        __syncthreads();
        #pragma unroll
        for (int k = 0; k < 8; k++) {
            float ar[4], br[4];
            #pragma unroll
            for (int i = 0; i < 4; i++) ar[i] = As[trow*4 + i][k];
            #pragma unroll
            for (int j = 0; j < 4; j++) br[j] = Bs[tcol*4 + j][k];
            #pragma unroll
            for (int i = 0; i < 4; i++)
                #pragma unroll
                for (int j = 0; j < 4; j++) acc[i][j] += ar[i] * br[j];
        }
        __syncthreads();
    }
    #pragma unroll
    for (int i = 0; i < 4; i++) {
        int row = by*64 + trow*4 + i;
        #pragma unroll
        for (int j = 0; j < 4; j++)
            C[(size_t)row*64 + tcol*4 + j] = acc[i][j];
    }
}

// ---------------- fp32 fallback GEMM (dt_proj) ---------------------
#define GBM 128
#define GBN 128
#define GBK 8
#define GTM 8
#define GTN 8

__global__ __launch_bounds__(256) void sgemm_nt(
    int M, int N, int K,
    const float* __restrict__ A, int lda,
    const float* __restrict__ B, int ldb,
    float* __restrict__ C, int ldc,
    const float* __restrict__ bias, int act)
{
    __shared__ float As[GBK][GBM];
    __shared__ float Bs[GBK][GBN];
    const int tid  = threadIdx.x;
    const int bx   = blockIdx.x, by = blockIdx.y;
    const int tcol = tid % 16;
    const int trow = tid / 16;
    const int aRow = tid >> 1;
    const int aCol = (tid & 1) << 2;

    float acc[GTM][GTN];
    #pragma unroll
    for (int i = 0; i < GTM; i++)
        #pragma unroll
        for (int j = 0; j < GTN; j++) acc[i][j] = 0.f;

    const float* Abase = A + (size_t)(by*GBM + aRow) * lda + aCol;
    const int nIdx = bx*GBN + aRow;
    const float* Bbase = B + (size_t)nIdx * ldb + aCol;
    const bool bOK = (nIdx < N);

    for (int k0 = 0; k0 < K; k0 += GBK) {
        float4 av = *(const float4*)(Abase + k0);
        float4 bv = bOK ? *(const float4*)(Bbase + k0) : make_float4(0.f,0.f,0.f,0.f);
        As[aCol+0][aRow] = av.x; As[aCol+1][aRow] = av.y;
        As[aCol+2][aRow] = av.z; As[aCol+3][aRow] = av.w;
        Bs[aCol+0][aRow] = bv.x; Bs[aCol+1][aRow] = bv.y;
        Bs[aCol+2][aRow] = bv.z; Bs[aCol+3][aRow] = bv.w;
        __syncthreads();
        #pragma unroll
        for (int k = 0; k < GBK; k++) {
            float ar[GTM], br[GTN];
            #pragma unroll
            for (int i = 0; i < GTM; i++) ar[i] = As[k][trow*GTM + i];
            #pragma unroll
            for (int j = 0; j < GTN; j++) br[j] = Bs[k][tcol*GTN + j];
            #pragma unroll
            for (int i = 0; i < GTM; i++)
                #pragma unroll
                for (int j = 0; j < GTN; j++)
                    acc[i][j] += ar[i] * br[j];
        }
        __syncthreads();
    }
    #pragma unroll
    for (int i = 0; i < GTM; i++) {
        int row = by*GBM + trow*GTM + i;
        #pragma unroll
        for (int j = 0; j < GTN; j++) {
            int col = bx*GBN + tcol*GTN + j;
            if (col < N) {
                float v = acc[i][j];
                if (bias) v += bias[col];
                if (act == 1) v = (v > 20.f) ? v : log1pf(__expf(v));
                C[(size_t)row*ldc + col] = v;
            }
        }
    }
}

// ---------------- host ----------------
static float* sym(const void* s) {
    void* p = nullptr;
    cudaGetSymbolAddress(&p, s);
    return (float*)p;
}

extern "C" void kernel_launch(void* const* d_in, const int* in_sizes, int n_in,
                              void* d_out, int out_size) {
    const float* spt       = (const float*)d_in[0];
    const float* qry       = (const float*)d_in[1];
    const float* conv_w    = (const float*)d_in[2];
    const float* conv_b    = (const float*)d_in[3];
    const float* ln_w      = (const float*)d_in[4];
    const float* ln_b      = (const float*)d_in[5];
    const float* in_proj_w = (const float*)d_in[6];
    const float* conv1d_w  = (const float*)d_in[7];
    const float* conv1d_b  = (const float*)d_in[8];
    const float* x_proj_w  = (const float*)d_in[9];
    const float* dt_proj_w = (const float*)d_in[10];
    const float* dt_proj_b = (const float*)d_in[11];
    const float* A_log     = (const float*)d_in[12];
    const float* D_skip    = (const float*)d_in[13];
    const float* out_proj_w= (const float*)d_in[14];
    const float* mlp_a_w   = (const float*)d_in[15];
    const float* mlp_a_b   = (const float*)d_in[16];
    const float* mlp_b_w   = (const float*)d_in[17];
    const float* mlp_b_b   = (const float*)d_in[18];
    float* out = (float*)d_out;

    float* p_fts0 = sym(g_fts0);
    float* p_wcat = sym(g_wcat);
    float* p_conv = sym(g_conv);
    float* p_F    = sym(g_F);
    float* p_xz   = sym(g_xz);
    float* p_xact = sym(g_xact);
    float* p_dbc  = sym(g_dbc);
    float* p_dt   = sym(g_dt);
    float* p_ys   = sym(g_ys);
    float* p_m    = sym(g_m);
    float* p_fts2 = sym(g_fts2);

    // 1. concat/reshape inputs -> fts0 (b,l,d)
    k_concat<<<(MROWS*CDIM + 255)/256, 256>>>(spt, qry);
    // 2. repack conv weights
    k_wcat<<<(CDIM*KCAT + 255)/256, 256>>>(conv_w);
    // 3. dense conv as bf16 GEMM with fused im2col: (8192,1536)x(512,1536)^T
    gemm_bf16<<<dim3(CDIM/TBN, MROWS/TBM), 256>>>(
        MROWS, CDIM, KCAT, p_fts0, 512, p_wcat, KCAT, p_conv, CDIM, conv_b, 1);
    // 4. LN + relu -> F
    k_ln<<<MROWS, 256>>>(p_conv, nullptr, ln_w, ln_b, p_F, 1);
    // 5. in_proj bf16: (8192,512)x(2048,512)^T -> xz
    gemm_bf16<<<dim3((2*DI)/TBN, MROWS/TBM), 256>>>(
        MROWS, 2*DI, CDIM, p_F, CDIM, in_proj_w, CDIM, p_xz, 2*DI, nullptr, 0);
    // 6. depthwise causal conv + silu -> xact
    k_dwconv<<<(MROWS*DI + 255)/256, 256>>>(conv1d_w, conv1d_b);
    // 7. x_proj fp32 (64x64 tiles): (8192,1024)x(64,1024)^T -> dbc
    sgemm64<<<dim3(1, MROWS/64), 256>>>(MROWS, DI, p_xact, DI, x_proj_w, DI, p_dbc);
    // 8. dt_proj + softplus fp32: (8192,32)x(1024,32)^T -> dt
    sgemm_nt<<<dim3(DI/GBN, MROWS/GBM), 256>>>(
        MROWS, DI, DTR, p_dbc, 64, dt_proj_w, DTR, p_dt, DI, dt_proj_b, 1);
    // 9. selective scan -> ys
    k_scan<<<dim3(DI/256, BB), 256>>>(A_log, D_skip);
    // 10. out_proj bf16: (8192,1024)x(512,1024)^T -> m
    gemm_bf16<<<dim3(CDIM/TBN, MROWS/TBM), 256>>>(
        MROWS, CDIM, DI, p_ys, DI, out_proj_w, DI, p_m, CDIM, nullptr, 0);
    // 11. residual + LN -> fts2
    k_ln<<<MROWS, 256>>>(p_m, p_F, ln_w, ln_b, p_fts2, 0);
    // 12/13. MLP head -> sigmoid
    k_coff<<<MROWS, 128>>>(mlp_a_w, mlp_a_b);
    k_out<<<BB, 128>>>(mlp_b_w, mlp_b_b, out);
}

// round 8
// speedup vs baseline: 2.9821x; 1.0537x over previous
#include <cuda_runtime.h>
#include <cuda_bf16.h>
#include <math.h>

#define BB   64
#define LLEN 128
#define CDIM 512
#define DI   1024
#define DS   16
#define DTR  32
#define MROWS (BB*LLEN)   // 8192
#define KCAT  (CDIM*3)    // 1536

// ---------------- scratch ----------------
__device__ float g_wcat[CDIM*KCAT];
__device__ float g_conv[MROWS*CDIM];
__device__ float g_F   [MROWS*CDIM];
__device__ float g_xz  [MROWS*2*DI];
__device__ float g_xact[MROWS*DI];
__device__ float g_dbc [MROWS*64];
__device__ float g_dt  [MROWS*DI];
__device__ float g_ys  [MROWS*DI];
__device__ float g_m   [MROWS*CDIM];
__device__ float g_fts2[MROWS*CDIM];
__device__ float g_coff[MROWS];

// ---------------- elementwise / prep kernels ----------------

// Wcat[o, k*512+i] = conv_w[o, i, k]
__global__ void k_wcat(const float* __restrict__ cw) {
    int idx = blockIdx.x * blockDim.x + threadIdx.x;
    if (idx >= CDIM*KCAT) return;
    int o = idx / KCAT, kk = idx % KCAT;
    int k = kk >> 9, i = kk & 511;
    g_wcat[idx] = cw[o*KCAT + i*3 + k];
}

// LayerNorm over 512 channels; optional residual; optional relu. 128 thr, float4.
__global__ __launch_bounds__(128) void k_ln(const float* __restrict__ x,
                                            const float* __restrict__ res,
                                            const float* __restrict__ w,
                                            const float* __restrict__ bb,
                                            float* __restrict__ out, int relu)
{
    int row = blockIdx.x;
    int t = threadIdx.x;
    const float4* xp = (const float4*)(x + (size_t)row*CDIM);
    float4 a = xp[t];
    if (res) {
        float4 r4 = ((const float4*)(res + (size_t)row*CDIM))[t];
        a.x += r4.x; a.y += r4.y; a.z += r4.z; a.w += r4.w;
    }
    float s = a.x + a.y + a.z + a.w;
    float q = a.x*a.x + a.y*a.y + a.z*a.z + a.w*a.w;
    __shared__ float shs[4], shq[4];
    int lane = t & 31, wid = t >> 5;
    #pragma unroll
    for (int o = 16; o; o >>= 1) {
        s += __shfl_xor_sync(0xffffffffu, s, o);
        q += __shfl_xor_sync(0xffffffffu, q, o);
    }
    if (lane == 0) { shs[wid] = s; shq[wid] = q; }
    __syncthreads();
    s = shs[0] + shs[1] + shs[2] + shs[3];
    q = shq[0] + shq[1] + shq[2] + shq[3];
    float mu  = s * (1.f/512.f);
    float var = q * (1.f/512.f) - mu*mu;
    float inv = rsqrtf(var + 1e-5f);
    float4 w4 = ((const float4*)w)[t];
    float4 b4 = ((const float4*)bb)[t];
    float4 o4;
    o4.x = (a.x - mu)*inv*w4.x + b4.x;
    o4.y = (a.y - mu)*inv*w4.y + b4.y;
    o4.z = (a.z - mu)*inv*w4.z + b4.z;
    o4.w = (a.w - mu)*inv*w4.w + b4.w;
    if (relu) {
        o4.x = fmaxf(o4.x, 0.f); o4.y = fmaxf(o4.y, 0.f);
        o4.z = fmaxf(o4.z, 0.f); o4.w = fmaxf(o4.w, 0.f);
    }
    ((float4*)(out + (size_t)row*CDIM))[t] = o4;
}

// depthwise causal conv1d (k=4, pad 3) + SiLU; 4 channels per thread (float4)
__global__ void k_dwconv(const float* __restrict__ w1, const float* __restrict__ b1) {
    int idx = blockIdx.x * blockDim.x + threadIdx.x;
    if (idx >= MROWS*(DI/4)) return;
    int c4 = (idx & 255) << 2;
    int m  = idx >> 8;
    int l  = m & 127;
    float4 wv[4];
    #pragma unroll
    for (int j = 0; j < 4; j++) wv[j] = *(const float4*)(w1 + (c4 + j)*4);
    const float* wf = (const float*)wv;   // wf[j*4 + k]
    float4 acc = *(const float4*)(b1 + c4);
    #pragma unroll
    for (int k = 0; k < 4; k++) {
        if (l + k - 3 >= 0) {
            float4 xv = *(const float4*)(&g_xz[(size_t)(m + k - 3)*(2*DI) + c4]);
            acc.x += wf[0*4 + k] * xv.x;
            acc.y += wf[1*4 + k] * xv.y;
            acc.z += wf[2*4 + k] * xv.z;
            acc.w += wf[3*4 + k] * xv.w;
        }
    }
    acc.x = acc.x / (1.f + __expf(-acc.x));
    acc.y = acc.y / (1.f + __expf(-acc.y));
    acc.z = acc.z / (1.f + __expf(-acc.z));
    acc.w = acc.w / (1.f + __expf(-acc.w));
    *(float4*)(&g_xact[(size_t)m*DI + c4]) = acc;
}

// selective scan (+D skip, +silu(z) gate). Uses power-chain when A[d,n] =
// (n+1)*A[d,0] (true for this dataset's A_log); generic exp fallback otherwise.
__global__ __launch_bounds__(256) void k_scan(const float* __restrict__ A_log,
                                              const float* __restrict__ D_skip)
{
    __shared__ float sB[LLEN][DS];
    __shared__ float sC[LLEN][DS];
    int b = blockIdx.y;
    int d = blockIdx.x * 256 + threadIdx.x;
    for (int i = threadIdx.x; i < LLEN*DS; i += 256) {
        int l = i >> 4, n = i & 15;
        sB[l][n] = g_dbc[(size_t)((b<<7)+l)*64 + 32 + n];
        sC[l][n] = g_dbc[(size_t)((b<<7)+l)*64 + 48 + n];
    }
    __syncthreads();
    float Ad[DS];
    #pragma unroll
    for (int n = 0; n < DS; n++) Ad[n] = -__expf(A_log[d*DS + n]);
    float Dv = D_skip[d];
    bool chain = true;
    #pragma unroll
    for (int n = 1; n < DS; n++)
        chain = chain && (fabsf(Ad[n] - (n+1)*Ad[0]) <= 1e-4f*(float)(n+1));
    float h[DS];
    #pragma unroll
    for (int n = 0; n < DS; n++) h[n] = 0.f;

    if (chain) {
        for (int l = 0; l < LLEN; l++) {
            size_t off = (size_t)(b<<7) + l;
            float dtv = g_dt  [off*DI + d];
            float xv  = g_xact[off*DI + d];
            float zv  = g_xz  [off*(2*DI) + DI + d];
            float dx = dtv * xv;
            float p = __expf(dtv * Ad[0]);
            float wmul = 1.f;
            float acc = 0.f;
            #pragma unroll
            for (int n = 0; n < DS; n++) {
                wmul *= p;
                h[n] = wmul * h[n] + dx * sB[l][n];
                acc += h[n] * sC[l][n];
            }
            float yv = acc + xv * Dv;
            float sz = zv / (1.f + __expf(-zv));
            g_ys[off*DI + d] = yv * sz;
        }
    } else {
        for (int l = 0; l < LLEN; l++) {
            size_t off = (size_t)(b<<7) + l;
            float dtv = g_dt  [off*DI + d];
            float xv  = g_xact[off*DI + d];
            float zv  = g_xz  [off*(2*DI) + DI + d];
            float dx = dtv * xv;
            float acc = 0.f;
            #pragma unroll
            for (int n = 0; n < DS; n++) {
                h[n] = __expf(dtv * Ad[n]) * h[n] + dx * sB[l][n];
                acc += h[n] * sC[l][n];
            }
            float yv = acc + xv * Dv;
            float sz = zv / (1.f + __expf(-zv));
            g_ys[off*DI + d] = yv * sz;
        }
    }
}

__global__ void k_coff(const float* __restrict__ aw, const float* __restrict__ ab) {
    int row = blockIdx.x, t = threadIdx.x;
    const float* xp = g_fts2 + (size_t)row * CDIM;
    float s = 0.f;
    #pragma unroll
    for (int i = 0; i < 4; i++) s += xp[t + i*128] * aw[t + i*128];
    __shared__ float sh[4];
    int lane = t & 31, wid = t >> 5;
    #pragma unroll
    for (int o = 16; o; o >>= 1) s += __shfl_xor_sync(0xffffffffu, s, o);
    if (lane == 0) sh[wid] = s;
    __syncthreads();
    if (t == 0) g_coff[row] = sh[0] + sh[1] + sh[2] + sh[3] + ab[0];
}

__global__ void k_out(const float* __restrict__ bw, const float* __restrict__ bbias,
                      float* __restrict__ out) {
    int b = blockIdx.x, t = threadIdx.x;
    float s = g_coff[b*128 + t] * bw[t];
    __shared__ float sh[4];
    int lane = t & 31, wid = t >> 5;
    #pragma unroll
    for (int o = 16; o; o >>= 1) s += __shfl_xor_sync(0xffffffffu, s, o);
    if (lane == 0) sh[wid] = s;
    __syncthreads();
    if (t == 0) {
        float v = sh[0] + sh[1] + sh[2] + sh[3] + bbias[0];
        out[b] = 1.f / (1.f + __expf(-v));
    }
}

// ================= BF16 tensor-core GEMM (ldmatrix frags) ====================
// C[M,N] = A[M,K]*B[N,K]^T, fp32 in/out. 128x128 tile, BK=32, double-buffered,
// 8 warps (4m x 2n), warp tile 32x64, mma.m16n8k16.bf16 + ldmatrix.x4.
// convMode=1: A = concat(spt,qry) with fused im2col (shift s = k0>>9).

#define TBM 128
#define TBN 128
#define TBK 32
#define HLD 20               // uints per smem row; 80B stride -> ldsm conflict-free
#define BUFB (TBM*HLD*4)     // bytes per smem buffer

__device__ __forceinline__ void ldsm_x4(unsigned addr, unsigned &r0, unsigned &r1,
                                        unsigned &r2, unsigned &r3) {
    asm volatile("ldmatrix.sync.aligned.m8n8.x4.shared.b16 {%0,%1,%2,%3}, [%4];"
                 : "=r"(r0), "=r"(r1), "=r"(r2), "=r"(r3) : "r"(addr));
}

__global__ __launch_bounds__(256) void gemm_bf16(
    int M, int N, int K,
    const float* __restrict__ A, int lda,
    const float* __restrict__ B, int ldb,
    float* __restrict__ C, int ldc,
    const float* __restrict__ bias, int convMode,
    const float* __restrict__ spt, const float* __restrict__ qry)
{
    __shared__ unsigned As[2][TBM*HLD];
    __shared__ unsigned Bs[2][TBN*HLD];

    const int tid  = threadIdx.x;
    const int lane = tid & 31;
    const int wid  = tid >> 5;
    const int wm   = wid & 3;
    const int wn   = wid >> 2;
    const int bx = blockIdx.x, by = blockIdx.y;

    float acc[2][8][4];
    #pragma unroll
    for (int i = 0; i < 2; i++)
        #pragma unroll
        for (int j = 0; j < 8; j++)
            #pragma unroll
            for (int v = 0; v < 4; v++) acc[i][j][v] = 0.f;

    // ldmatrix per-lane addresses (buf 0, ks 0)
    const int g  = lane >> 3;
    const int lr = lane & 7;
    unsigned aBase = (unsigned)__cvta_generic_to_shared(&As[0][0]);
    unsigned bBase = (unsigned)__cvta_generic_to_shared(&Bs[0][0]);
    unsigned aAddr[2], bAddr[4];
    #pragma unroll
    for (int mt = 0; mt < 2; mt++) {
        int row = wm*32 + mt*16 + lr + ((g & 1) << 3);
        aAddr[mt] = aBase + row*HLD*4 + ((g >> 1) << 4);
    }
    #pragma unroll
    for (int p = 0; p < 4; p++) {
        int row = wn*64 + p*16 + lr + ((g >> 1) << 3);
        bAddr[p] = bBase + row*HLD*4 + ((g & 1) << 4);
    }

    auto loadA = [&](int kt, float4 av[4]) {
        int k0 = kt * TBK;
        #pragma unroll
        for (int i = 0; i < 4; i++) {
            int p   = tid + i*256;
            int row = p >> 3;
            int kq  = (p & 7) << 2;
            if (!convMode) {
                av[i] = *(const float4*)(A + (size_t)(by*TBM + row)*lda + k0 + kq);
            } else {
                int m  = by*TBM + row;
                int l  = m & 127;
                int s  = k0 >> 9;
                int lp = l + s - 1;
                int b  = m >> 7;
                int col = (k0 & 511) + kq;
                if ((unsigned)lp < 64u)
                    av[i] = *(const float4*)(spt + (size_t)b*32768 + lp*512 + col);
                else if ((unsigned)lp < 128u)
                    av[i] = *(const float4*)(qry + (size_t)b*32768 + (lp-64)*512 + col);
                else
                    av[i] = make_float4(0.f, 0.f, 0.f, 0.f);
            }
        }
    };
    auto loadB = [&](int kt, float4 bv[4]) {
        int k0 = kt * TBK;
        #pragma unroll
        for (int i = 0; i < 4; i++) {
            int p   = tid + i*256;
            int row = p >> 3;
            int kq  = (p & 7) << 2;
            bv[i] = *(const float4*)(B + (size_t)(bx*TBN + row)*ldb + k0 + kq);
        }
    };
    auto stage = [&](int buf, const float4 av[4], const float4 bv[4]) {
        #pragma unroll
        for (int i = 0; i < 4; i++) {
            int p   = tid + i*256;
            int row = p >> 3;
            int kq2 = (p & 7) << 1;
            __nv_bfloat162 a0 = __float22bfloat162_rn(make_float2(av[i].x, av[i].y));
            __nv_bfloat162 a1 = __float22bfloat162_rn(make_float2(av[i].z, av[i].w));
            __nv_bfloat162 b0 = __float22bfloat162_rn(make_float2(bv[i].x, bv[i].y));
            __nv_bfloat162 b1 = __float22bfloat162_rn(make_float2(bv[i].z, bv[i].w));
            *(uint2*)&As[buf][row*HLD + kq2] =
                make_uint2(*(unsigned*)&a0, *(unsigned*)&a1);
            *(uint2*)&Bs[buf][row*HLD + kq2] =
                make_uint2(*(unsigned*)&b0, *(unsigned*)&b1);
        }
    };

    float4 avr[4], bvr[4];
    loadA(0, avr); loadB(0, bvr);
    stage(0, avr, bvr);
    __syncthreads();

    const int KT = K / TBK;
    for (int kt = 0; kt < KT; kt++) {
        int cur = kt & 1;
        if (kt + 1 < KT) { loadA(kt+1, avr); loadB(kt+1, bvr); }

        #pragma unroll
        for (int ks = 0; ks < 2; ks++) {
            int off = cur*BUFB + ks*32;
            unsigned af[2][4], bf[8][2];
            ldsm_x4(aAddr[0] + off, af[0][0], af[0][1], af[0][2], af[0][3]);
            ldsm_x4(aAddr[1] + off, af[1][0], af[1][1], af[1][2], af[1][3]);
            #pragma unroll
            for (int p = 0; p < 4; p++)
                ldsm_x4(bAddr[p] + off, bf[2*p][0], bf[2*p][1],
                                        bf[2*p+1][0], bf[2*p+1][1]);
            #pragma unroll
            for (int mt = 0; mt < 2; mt++)
                #pragma unroll
                for (int nt = 0; nt < 8; nt++) {
                    asm volatile(
                        "mma.sync.aligned.m16n8k16.row.col.f32.bf16.bf16.f32 "
                        "{%0,%1,%2,%3},{%4,%5,%6,%7},{%8,%9},{%0,%1,%2,%3};"
                        : "+f"(acc[mt][nt][0]), "+f"(acc[mt][nt][1]),
                          "+f"(acc[mt][nt][2]), "+f"(acc[mt][nt][3])
                        : "r"(af[mt][0]), "r"(af[mt][1]),
                          "r"(af[mt][2]), "r"(af[mt][3]),
                          "r"(bf[nt][0]), "r"(bf[nt][1]));
                }
        }

        if (kt + 1 < KT) {
            stage(cur ^ 1, avr, bvr);
            __syncthreads();
        }
    }

    #pragma unroll
    for (int mt = 0; mt < 2; mt++) {
        int r0 = by*TBM + wm*32 + mt*16 + (lane >> 2);
        #pragma unroll
        for (int nt = 0; nt < 8; nt++) {
            int c = bx*TBN + wn*64 + nt*8 + 2*(lane & 3);
            float bb0 = bias ? bias[c]   : 0.f;
            float bb1 = bias ? bias[c+1] : 0.f;
            float2 v0 = make_float2(acc[mt][nt][0] + bb0, acc[mt][nt][1] + bb1);
            float2 v1 = make_float2(acc[mt][nt][2] + bb0, acc[mt][nt][3] + bb1);
            *(float2*)(C + (size_t) r0     *ldc + c) = v0;
            *(float2*)(C + (size_t)(r0 + 8)*ldc + c) = v1;
        }
    }
}

// ---------------- fp32 64x64-tile GEMM (x_proj: M=8192, N=64, K=1024) -------
__global__ __launch_bounds__(256) void sgemm64(
    int M, int K,
    const float* __restrict__ A, int lda,
    const float* __restrict__ B, int ldb,
    float* __restrict__ C)
{
    __shared__ float As[64][10];
    __shared__ float Bs[64][10];
    const int tid  = threadIdx.x;
    const int by   = blockIdx.y;
    const int trow = tid >> 4;
    const int tcol = tid & 15;
    const int aRow = tid >> 2;
    const int aCol = (tid & 3) << 1;

    float acc[4][4];
    #pragma unroll
    for (int i = 0; i < 4; i++)
        #pragma unroll
        for (int j = 0; j < 4; j++) acc[i][j] = 0.f;

    const float* Ab = A + (size_t)(by*64 + aRow)*lda + aCol;
    const float* Bb = B + (size_t)aRow*ldb + aCol;

    for (int k0 = 0; k0 < K; k0 += 8) {
        float2 av = *(const float2*)(Ab + k0);
        float2 bv = *(const float2*)(Bb + k0);
        As[aRow][aCol] = av.x; As[aRow][aCol+1] = av.y;
        Bs[aRow][aCol] = bv.x; Bs[aRow][aCol+1] = bv.y;
        __syncthreads();
        #pragma unroll
        for (int k = 0; k < 8; k++) {
            float ar[4], br[4];
            #pragma unroll
            for (int i = 0; i < 4; i++) ar[i] = As[trow*4 + i][k];
            #pragma unroll
            for (int j = 0; j < 4; j++) br[j] = Bs[tcol*4 + j][k];
            #pragma unroll
            for (int i = 0; i < 4; i++)
                #pragma unroll
                for (int j = 0; j < 4; j++) acc[i][j] += ar[i] * br[j];
        }
        __syncthreads();
    }
    #pragma unroll
    for (int i = 0; i < 4; i++) {
        int row = by*64 + trow*4 + i;
        #pragma unroll
        for (int j = 0; j < 4; j++)
            C[(size_t)row*64 + tcol*4 + j] = acc[i][j];
    }
}

// ---------------- fp32 fallback GEMM (dt_proj) ---------------------
#define GBM 128
#define GBN 128
#define GBK 8
#define GTM 8
#define GTN 8

__global__ __launch_bounds__(256) void sgemm_nt(
    int M, int N, int K,
    const float* __restrict__ A, int lda,
    const float* __restrict__ B, int ldb,
    float* __restrict__ C, int ldc,
    const float* __restrict__ bias, int act)
{
    __shared__ float As[GBK][GBM];
    __shared__ float Bs[GBK][GBN];
    const int tid  = threadIdx.x;
    const int bx   = blockIdx.x, by = blockIdx.y;
    const int tcol = tid % 16;
    const int trow = tid / 16;
    const int aRow = tid >> 1;
    const int aCol = (tid & 1) << 2;

    float acc[GTM][GTN];
    #pragma unroll
    for (int i = 0; i < GTM; i++)
        #pragma unroll
        for (int j = 0; j < GTN; j++) acc[i][j] = 0.f;

    const float* Abase = A + (size_t)(by*GBM + aRow) * lda + aCol;
    const int nIdx = bx*GBN + aRow;
    const float* Bbase = B + (size_t)nIdx * ldb + aCol;
    const bool bOK = (nIdx < N);

    for (int k0 = 0; k0 < K; k0 += GBK) {
        float4 av = *(const float4*)(Abase + k0);
        float4 bv = bOK ? *(const float4*)(Bbase + k0) : make_float4(0.f,0.f,0.f,0.f);
        As[aCol+0][aRow] = av.x; As[aCol+1][aRow] = av.y;
        As[aCol+2][aRow] = av.z; As[aCol+3][aRow] = av.w;
        Bs[aCol+0][aRow] = bv.x; Bs[aCol+1][aRow] = bv.y;
        Bs[aCol+2][aRow] = bv.z; Bs[aCol+3][aRow] = bv.w;
        __syncthreads();
        #pragma unroll
        for (int k = 0; k < GBK; k++) {
            float ar[GTM], br[GTN];
            #pragma unroll
            for (int i = 0; i < GTM; i++) ar[i] = As[k][trow*GTM + i];
            #pragma unroll
            for (int j = 0; j < GTN; j++) br[j] = Bs[k][tcol*GTN + j];
            #pragma unroll
            for (int i = 0; i < GTM; i++)
                #pragma unroll
                for (int j = 0; j < GTN; j++)
                    acc[i][j] += ar[i] * br[j];
        }
        __syncthreads();
    }
    #pragma unroll
    for (int i = 0; i < GTM; i++) {
        int row = by*GBM + trow*GTM + i;
        #pragma unroll
        for (int j = 0; j < GTN; j++) {
            int col = bx*GBN + tcol*GTN + j;
            if (col < N) {
                float v = acc[i][j];
                if (bias) v += bias[col];
                if (act == 1) v = (v > 20.f) ? v : log1pf(__expf(v));
                C[(size_t)row*ldc + col] = v;
            }
        }
    }
}

// ---------------- host ----------------
static float* sym(const void* s) {
    void* p = nullptr;
    cudaGetSymbolAddress(&p, s);
    return (float*)p;
}

extern "C" void kernel_launch(void* const* d_in, const int* in_sizes, int n_in,
                              void* d_out, int out_size) {
    const float* spt       = (const float*)d_in[0];
    const float* qry       = (const float*)d_in[1];
    const float* conv_w    = (const float*)d_in[2];
    const float* conv_b    = (const float*)d_in[3];
    const float* ln_w      = (const float*)d_in[4];
    const float* ln_b      = (const float*)d_in[5];
    const float* in_proj_w = (const float*)d_in[6];
    const float* conv1d_w  = (const float*)d_in[7];
    const float* conv1d_b  = (const float*)d_in[8];
    const float* x_proj_w  = (const float*)d_in[9];
    const float* dt_proj_w = (const float*)d_in[10];
    const float* dt_proj_b = (const float*)d_in[11];
    const float* A_log     = (const float*)d_in[12];
    const float* D_skip    = (const float*)d_in[13];
    const float* out_proj_w= (const float*)d_in[14];
    const float* mlp_a_w   = (const float*)d_in[15];
    const float* mlp_a_b   = (const float*)d_in[16];
    const float* mlp_b_w   = (const float*)d_in[17];
    const float* mlp_b_b   = (const float*)d_in[18];
    float* out = (float*)d_out;

    float* p_wcat = sym(g_wcat);
    float* p_conv = sym(g_conv);
    float* p_F    = sym(g_F);
    float* p_xz   = sym(g_xz);
    float* p_xact = sym(g_xact);
    float* p_dbc  = sym(g_dbc);
    float* p_dt   = sym(g_dt);
    float* p_ys   = sym(g_ys);
    float* p_m    = sym(g_m);
    float* p_fts2 = sym(g_fts2);

    // 1. repack conv weights
    k_wcat<<<(CDIM*KCAT + 255)/256, 256>>>(conv_w);
    // 2. dense conv as bf16 GEMM, fused im2col + concat: (8192,1536)x(512,1536)^T
    gemm_bf16<<<dim3(CDIM/TBN, MROWS/TBM), 256>>>(
        MROWS, CDIM, KCAT, nullptr, 0, p_wcat, KCAT, p_conv, CDIM, conv_b, 1,
        spt, qry);
    // 3. LN + relu -> F
    k_ln<<<MROWS, 128>>>(p_conv, nullptr, ln_w, ln_b, p_F, 1);
    // 4. in_proj bf16: (8192,512)x(2048,512)^T -> xz
    gemm_bf16<<<dim3((2*DI)/TBN, MROWS/TBM), 256>>>(
        MROWS, 2*DI, CDIM, p_F, CDIM, in_proj_w, CDIM, p_xz, 2*DI, nullptr, 0,
        nullptr, nullptr);
    // 5. depthwise causal conv + silu -> xact
    k_dwconv<<<(MROWS*(DI/4) + 255)/256, 256>>>(conv1d_w, conv1d_b);
    // 6. x_proj fp32: (8192,1024)x(64,1024)^T -> dbc
    sgemm64<<<dim3(1, MROWS/64), 256>>>(MROWS, DI, p_xact, DI, x_proj_w, DI, p_dbc);
    // 7. dt_proj + softplus fp32: (8192,32)x(1024,32)^T -> dt
    sgemm_nt<<<dim3(DI/GBN, MROWS/GBM), 256>>>(
        MROWS, DI, DTR, p_dbc, 64, dt_proj_w, DTR, p_dt, DI, dt_proj_b, 1);
    // 8. selective scan -> ys
    k_scan<<<dim3(DI/256, BB), 256>>>(A_log, D_skip);
    // 9. out_proj bf16: (8192,1024)x(512,1024)^T -> m
    gemm_bf16<<<dim3(CDIM/TBN, MROWS/TBM), 256>>>(
        MROWS, CDIM, DI, p_ys, DI, out_proj_w, DI, p_m, CDIM, nullptr, 0,
        nullptr, nullptr);
    // 10. residual + LN -> fts2
    k_ln<<<MROWS, 128>>>(p_m, p_F, ln_w, ln_b, p_fts2, 0);
    // 11/12. MLP head -> sigmoid
    k_coff<<<MROWS, 128>>>(mlp_a_w, mlp_a_b);
    k_out<<<BB, 128>>>(mlp_b_w, mlp_b_b, out);
}

// round 11
// speedup vs baseline: 4.1797x; 1.4016x over previous
#include <cuda_runtime.h>
#include <cuda_bf16.h>
#include <math.h>

#define BB   64
#define LLEN 128
#define CDIM 512
#define DI   1024
#define DS   16
#define DTR  32
#define MROWS 8192
#define KCAT  1536

// ---------------- fp32 scratch ----------------
__device__ float g_conv[MROWS*CDIM];
__device__ float g_F   [MROWS*CDIM];
__device__ float g_xz  [MROWS*2*DI];
__device__ float g_xact[MROWS*DI];
__device__ float g_dbc [MROWS*64];
__device__ float g_dt  [MROWS*DI];
__device__ float g_m   [MROWS*CDIM];
__device__ float g_fts2[MROWS*CDIM];
__device__ float g_coff[MROWS];

// ---------------- bf16 scratch ----------------
__device__ __align__(16) __nv_bfloat16 h_fts0[MROWS*CDIM];
__device__ __align__(16) __nv_bfloat16 h_wcat[CDIM*KCAT];
__device__ __align__(16) __nv_bfloat16 h_inw [2*DI*CDIM];
__device__ __align__(16) __nv_bfloat16 h_xw  [64*DI];
__device__ __align__(16) __nv_bfloat16 h_dtw [DI*DTR];
__device__ __align__(16) __nv_bfloat16 h_outw[CDIM*DI];
__device__ __align__(16) __nv_bfloat16 h_F   [MROWS*CDIM];
__device__ __align__(16) __nv_bfloat16 h_xact[MROWS*DI];
__device__ __align__(16) __nv_bfloat16 h_dbc [MROWS*64];
__device__ __align__(16) __nv_bfloat16 h_ys  [MROWS*DI];

// ---------------- small helpers ----------------
__device__ __forceinline__ uint2 f4_to_bf4(float4 v) {
    __nv_bfloat162 p0 = __float22bfloat162_rn(make_float2(v.x, v.y));
    __nv_bfloat162 p1 = __float22bfloat162_rn(make_float2(v.z, v.w));
    return make_uint2(*(unsigned*)&p0, *(unsigned*)&p1);
}

// fp32 -> bf16, 4 elements per thread
__global__ void k_cvt(const float* __restrict__ s, __nv_bfloat16* __restrict__ d,
                      int n4) {
    int i = blockIdx.x * blockDim.x + threadIdx.x;
    if (i >= n4) return;
    ((uint2*)d)[i] = f4_to_bf4(((const float4*)s)[i]);
}

// concat(spt,qry) reshaped -> h_fts0 bf16
__global__ void k_concat_h(const float* __restrict__ spt, const float* __restrict__ qry) {
    int i4 = blockIdx.x * blockDim.x + threadIdx.x;
    if (i4 >= MROWS*CDIM/4) return;
    int idx = i4 << 2;
    int b = idx >> 16, r = idx & 65535;
    float4 v = (r < 32768) ? *(const float4*)(spt + (size_t)b*32768 + r)
                           : *(const float4*)(qry + (size_t)b*32768 + r - 32768);
    ((uint2*)h_fts0)[i4] = f4_to_bf4(v);
}

// Wcat[o, k*512+i] = conv_w[o, i, k]  (bf16)
__global__ void k_wcat_h(const float* __restrict__ cw) {
    int idx = blockIdx.x * blockDim.x + threadIdx.x;
    if (idx >= CDIM*KCAT) return;
    int o = idx / KCAT, kk = idx % KCAT;
    int k = kk >> 9, i = kk & 511;
    h_wcat[idx] = __float2bfloat16(cw[o*KCAT + i*3 + k]);
}

// LayerNorm over 512 ch; optional residual/relu; optional bf16 copy out.
__global__ __launch_bounds__(128) void k_ln(const float* __restrict__ x,
                                            const float* __restrict__ res,
                                            const float* __restrict__ w,
                                            const float* __restrict__ bb,
                                            float* __restrict__ out,
                                            __nv_bfloat16* __restrict__ outh,
                                            int relu)
{
    int row = blockIdx.x;
    int t = threadIdx.x;
    float4 a = ((const float4*)(x + (size_t)row*CDIM))[t];
    if (res) {
        float4 r4 = ((const float4*)(res + (size_t)row*CDIM))[t];
        a.x += r4.x; a.y += r4.y; a.z += r4.z; a.w += r4.w;
    }
    float s = a.x + a.y + a.z + a.w;
    float q = a.x*a.x + a.y*a.y + a.z*a.z + a.w*a.w;
    __shared__ float shs[4], shq[4];
    int lane = t & 31, wid = t >> 5;
    #pragma unroll
    for (int o = 16; o; o >>= 1) {
        s += __shfl_xor_sync(0xffffffffu, s, o);
        q += __shfl_xor_sync(0xffffffffu, q, o);
    }
    if (lane == 0) { shs[wid] = s; shq[wid] = q; }
    __syncthreads();
    s = shs[0] + shs[1] + shs[2] + shs[3];
    q = shq[0] + shq[1] + shq[2] + shq[3];
    float mu  = s * (1.f/512.f);
    float var = q * (1.f/512.f) - mu*mu;
    float inv = rsqrtf(var + 1e-5f);
    float4 w4 = ((const float4*)w)[t];
    float4 b4 = ((const float4*)bb)[t];
    float4 o4;
    o4.x = (a.x - mu)*inv*w4.x + b4.x;
    o4.y = (a.y - mu)*inv*w4.y + b4.y;
    o4.z = (a.z - mu)*inv*w4.z + b4.z;
    o4.w = (a.w - mu)*inv*w4.w + b4.w;
    if (relu) {
        o4.x = fmaxf(o4.x, 0.f); o4.y = fmaxf(o4.y, 0.f);
        o4.z = fmaxf(o4.z, 0.f); o4.w = fmaxf(o4.w, 0.f);
    }
    ((float4*)(out + (size_t)row*CDIM))[t] = o4;
    if (outh) ((uint2*)(outh + (size_t)row*CDIM))[t] = f4_to_bf4(o4);
}

// depthwise causal conv1d (k=4, pad 3) + SiLU; writes fp32 + bf16
__global__ void k_dwconv(const float* __restrict__ w1, const float* __restrict__ b1) {
    int idx = blockIdx.x * blockDim.x + threadIdx.x;
    if (idx >= MROWS*(DI/4)) return;
    int c4 = (idx & 255) << 2;
    int m  = idx >> 8;
    int l  = m & 127;
    float4 wv[4];
    #pragma unroll
    for (int j = 0; j < 4; j++) wv[j] = *(const float4*)(w1 + (c4 + j)*4);
    const float* wf = (const float*)wv;
    float4 acc = *(const float4*)(b1 + c4);
    #pragma unroll
    for (int k = 0; k < 4; k++) {
        if (l + k - 3 >= 0) {
            float4 xv = *(const float4*)(&g_xz[(size_t)(m + k - 3)*(2*DI) + c4]);
            acc.x += wf[0*4 + k] * xv.x;
            acc.y += wf[1*4 + k] * xv.y;
            acc.z += wf[2*4 + k] * xv.z;
            acc.w += wf[3*4 + k] * xv.w;
        }
    }
    acc.x = acc.x / (1.f + __expf(-acc.x));
    acc.y = acc.y / (1.f + __expf(-acc.y));
    acc.z = acc.z / (1.f + __expf(-acc.z));
    acc.w = acc.w / (1.f + __expf(-acc.w));
    *(float4*)(&g_xact[(size_t)m*DI + c4]) = acc;
    *(uint2*)(&h_xact[(size_t)m*DI + c4]) = f4_to_bf4(acc);
}

// selective scan (+D skip, +silu(z) gate) -> bf16 ys. Power-chain fast path.
__global__ __launch_bounds__(256) void k_scan(const float* __restrict__ A_log,
                                              const float* __restrict__ D_skip)
{
    __shared__ float sB[LLEN][DS];
    __shared__ float sC[LLEN][DS];
    int b = blockIdx.y;
    int d = blockIdx.x * 256 + threadIdx.x;
    for (int i = threadIdx.x; i < LLEN*DS; i += 256) {
        int l = i >> 4, n = i & 15;
        sB[l][n] = g_dbc[(size_t)((b<<7)+l)*64 + 32 + n];
        sC[l][n] = g_dbc[(size_t)((b<<7)+l)*64 + 48 + n];
    }
    __syncthreads();
    float Ad[DS];
    #pragma unroll
    for (int n = 0; n < DS; n++) Ad[n] = -__expf(A_log[d*DS + n]);
    float Dv = D_skip[d];
    bool chain = true;
    #pragma unroll
    for (int n = 1; n < DS; n++)
        chain = chain && (fabsf(Ad[n] - (n+1)*Ad[0]) <= 1e-4f*(float)(n+1));
    float h[DS];
    #pragma unroll
    for (int n = 0; n < DS; n++) h[n] = 0.f;

    if (chain) {
        for (int l = 0; l < LLEN; l++) {
            size_t off = (size_t)(b<<7) + l;
            float dtv = g_dt  [off*DI + d];
            float xv  = g_xact[off*DI + d];
            float zv  = g_xz  [off*(2*DI) + DI + d];
            float dx = dtv * xv;
            float p = __expf(dtv * Ad[0]);
            float wmul = 1.f;
            float acc = 0.f;
            #pragma unroll
            for (int n = 0; n < DS; n++) {
                wmul *= p;
                h[n] = wmul * h[n] + dx * sB[l][n];
                acc += h[n] * sC[l][n];
            }
            float yv = acc + xv * Dv;
            float sz = zv / (1.f + __expf(-zv));
            h_ys[off*DI + d] = __float2bfloat16(yv * sz);
        }
    } else {
        for (int l = 0; l < LLEN; l++) {
            size_t off = (size_t)(b<<7) + l;
            float dtv = g_dt  [off*DI + d];
            float xv  = g_xact[off*DI + d];
            float zv  = g_xz  [off*(2*DI) + DI + d];
            float dx = dtv * xv;
            float acc = 0.f;
            #pragma unroll
            for (int n = 0; n < DS; n++) {
                h[n] = __expf(dtv * Ad[n]) * h[n] + dx * sB[l][n];
                acc += h[n] * sC[l][n];
            }
            float yv = acc + xv * Dv;
            float sz = zv / (1.f + __expf(-zv));
            h_ys[off*DI + d] = __float2bfloat16(yv * sz);
        }
    }
}

__global__ void k_coff(const float* __restrict__ aw, const float* __restrict__ ab) {
    int row = blockIdx.x, t = threadIdx.x;
    const float* xp = g_fts2 + (size_t)row * CDIM;
    float s = 0.f;
    #pragma unroll
    for (int i = 0; i < 4; i++) s += xp[t + i*128] * aw[t + i*128];
    __shared__ float sh[4];
    int lane = t & 31, wid = t >> 5;
    #pragma unroll
    for (int o = 16; o; o >>= 1) s += __shfl_xor_sync(0xffffffffu, s, o);
    if (lane == 0) sh[wid] = s;
    __syncthreads();
    if (t == 0) g_coff[row] = sh[0] + sh[1] + sh[2] + sh[3] + ab[0];
}

__global__ void k_out(const float* __restrict__ bw, const float* __restrict__ bbias,
                      float* __restrict__ out) {
    int b = blockIdx.x, t = threadIdx.x;
    float s = g_coff[b*128 + t] * bw[t];
    __shared__ float sh[4];
    int lane = t & 31, wid = t >> 5;
    #pragma unroll
    for (int o = 16; o; o >>= 1) s += __shfl_xor_sync(0xffffffffu, s, o);
    if (lane == 0) sh[wid] = s;
    __syncthreads();
    if (t == 0) {
        float v = sh[0] + sh[1] + sh[2] + sh[3] + bbias[0];
        out[b] = 1.f / (1.f + __expf(-v));
    }
}

// ============== bf16 GEMM, cp.async 4-stage pipeline, ldmatrix ===============
// C[M,N] = A[M,K]*B[N,K]^T. A,B bf16 in gmem; C fp32 (+ optional bf16 copy).
// 128x128 tile, BK=32, 8 warps (4m x 2n), warp tile 32x64, mma.m16n8k16.
// convMode=1: A = h_fts0 with fused im2col (shift = k0>>9). N-guard for N<128.
// act=1: softplus epilogue.

#define TBM 128
#define TBN 128
#define TBK 32
#define ROWB 80                 // bytes per smem row (64 data + 16 pad)
#define ASTAGE (TBM*ROWB)       // 10240
#define STAGES 4
#define GSMEM (2*STAGES*ASTAGE) // 81920

__device__ __forceinline__ void cp16(unsigned dst, const void* src, int sz) {
    asm volatile("cp.async.cg.shared.global [%0], [%1], 16, %2;"
                 :: "r"(dst), "l"(src), "r"(sz) : "memory");
}
__device__ __forceinline__ void cp_commit() {
    asm volatile("cp.async.commit_group;" ::: "memory");
}
__device__ __forceinline__ void cp_wait2() {
    asm volatile("cp.async.wait_group 2;" ::: "memory");
}
__device__ __forceinline__ void ldsm_x4(unsigned addr, unsigned &r0, unsigned &r1,
                                        unsigned &r2, unsigned &r3) {
    asm volatile("ldmatrix.sync.aligned.m8n8.x4.shared.b16 {%0,%1,%2,%3}, [%4];"
                 : "=r"(r0), "=r"(r1), "=r"(r2), "=r"(r3) : "r"(addr));
}

__global__ __launch_bounds__(256, 2) void gemm_h(
    int M, int N, int K,
    const __nv_bfloat16* __restrict__ A, int lda,
    const __nv_bfloat16* __restrict__ B, int ldb,
    float* __restrict__ C, int ldc,
    __nv_bfloat16* __restrict__ Ch,
    const float* __restrict__ bias, int act, int convMode)
{
    extern __shared__ __align__(16) unsigned char dynsm[];
    const unsigned aS = (unsigned)__cvta_generic_to_shared(dynsm);
    const unsigned bS = aS + STAGES*ASTAGE;

    const int tid  = threadIdx.x;
    const int lane = tid & 31;
    const int wid  = tid >> 5;
    const int wm   = wid & 3;
    const int wn   = wid >> 2;
    const int bx = blockIdx.x, by = blockIdx.y;

    float acc[2][8][4];
    #pragma unroll
    for (int i = 0; i < 2; i++)
        #pragma unroll
        for (int j = 0; j < 8; j++)
            #pragma unroll
            for (int v = 0; v < 4; v++) acc[i][j][v] = 0.f;

    // ldmatrix base addresses (stage 0, ks 0)
    const int g  = lane >> 3;
    const int lr = lane & 7;
    unsigned aAddr[2], bAddr[4];
    #pragma unroll
    for (int mt = 0; mt < 2; mt++) {
        int row = wm*32 + mt*16 + lr + ((g & 1) << 3);
        aAddr[mt] = aS + row*ROWB + ((g >> 1) << 4);
    }
    #pragma unroll
    for (int p = 0; p < 4; p++) {
        int row = wn*64 + p*16 + lr + ((g >> 1) << 3);
        bAddr[p] = bS + row*ROWB + ((g & 1) << 4);
    }

    auto issue = [&](int kt, int buf) {
        int k0 = kt * TBK;
        #pragma unroll
        for (int i = 0; i < 2; i++) {
            int p   = tid + i*256;   // 0..511
            int row = p >> 2;        // 0..127
            int seg = p & 3;         // 16B segment
            // A
            const __nv_bfloat16* asrc = A;
            int asz = 16;
            if (!convMode) {
                asrc = A + (size_t)(by*TBM + row)*lda + k0 + seg*8;
            } else {
                int m  = by*TBM + row;
                int l  = m & 127;
                int b  = m >> 7;
                int lp = l + (k0 >> 9) - 1;
                if ((unsigned)lp < 128u)
                    asrc = A + ((size_t)(b << 7) + lp)*512 + (k0 & 511) + seg*8;
                else
                    asz = 0;
            }
            cp16(aS + buf*ASTAGE + row*ROWB + seg*16, asrc, asz);
            // B
            int nrow = bx*TBN + row;
            const __nv_bfloat16* bsrc = B;
            int bsz = 16;
            if (nrow < N) bsrc = B + (size_t)nrow*ldb + k0 + seg*8;
            else          bsz = 0;
            cp16(bS + buf*ASTAGE + row*ROWB + seg*16, bsrc, bsz);
        }
    };

    const int KT = K / TBK;
    #pragma unroll
    for (int s = 0; s < STAGES-1; s++) {
        if (s < KT) issue(s, s);
        cp_commit();
    }

    for (int kt = 0; kt < KT; kt++) {
        int buf = kt & (STAGES-1);
        cp_wait2();
        __syncthreads();

        #pragma unroll
        for (int ks = 0; ks < 2; ks++) {
            unsigned off = buf*ASTAGE + ks*32;
            unsigned af[2][4], bf[8][2];
            ldsm_x4(aAddr[0] + off, af[0][0], af[0][1], af[0][2], af[0][3]);
            ldsm_x4(aAddr[1] + off, af[1][0], af[1][1], af[1][2], af[1][3]);
            #pragma unroll
            for (int p = 0; p < 4; p++)
                ldsm_x4(bAddr[p] + off, bf[2*p][0], bf[2*p][1],
                                        bf[2*p+1][0], bf[2*p+1][1]);
            #pragma unroll
            for (int mt = 0; mt < 2; mt++)
                #pragma unroll
                for (int nt = 0; nt < 8; nt++) {
                    asm volatile(
                        "mma.sync.aligned.m16n8k16.row.col.f32.bf16.bf16.f32 "
                        "{%0,%1,%2,%3},{%4,%5,%6,%7},{%8,%9},{%0,%1,%2,%3};"
                        : "+f"(acc[mt][nt][0]), "+f"(acc[mt][nt][1]),
                          "+f"(acc[mt][nt][2]), "+f"(acc[mt][nt][3])
                        : "r"(af[mt][0]), "r"(af[mt][1]),
                          "r"(af[mt][2]), "r"(af[mt][3]),
                          "r"(bf[nt][0]), "r"(bf[nt][1]));
                }
        }

        int nk = kt + STAGES - 1;
        if (nk < KT) issue(nk, nk & (STAGES-1));
        cp_commit();
    }

    // epilogue
    #pragma unroll
    for (int mt = 0; mt < 2; mt++) {
        int r0 = by*TBM + wm*32 + mt*16 + (lane >> 2);
        #pragma unroll
        for (int nt = 0; nt < 8; nt++) {
            int c = bx*TBN + wn*64 + nt*8 + 2*(lane & 3);
            if (c >= N) continue;
            float bb0 = bias ? bias[c]   : 0.f;
            float bb1 = bias ? bias[c+1] : 0.f;
            float v00 = acc[mt][nt][0] + bb0, v01 = acc[mt][nt][1] + bb1;
            float v10 = acc[mt][nt][2] + bb0, v11 = acc[mt][nt][3] + bb1;
            if (act == 1) {
                v00 = (v00 > 20.f) ? v00 : log1pf(__expf(v00));
                v01 = (v01 > 20.f) ? v01 : log1pf(__expf(v01));
                v10 = (v10 > 20.f) ? v10 : log1pf(__expf(v10));
                v11 = (v11 > 20.f) ? v11 : log1pf(__expf(v11));
            }
            *(float2*)(C + (size_t) r0     *ldc + c) = make_float2(v00, v01);
            *(float2*)(C + (size_t)(r0 + 8)*ldc + c) = make_float2(v10, v11);
            if (Ch) {
                __nv_bfloat162 h0 = __float22bfloat162_rn(make_float2(v00, v01));
                __nv_bfloat162 h1 = __float22bfloat162_rn(make_float2(v10, v11));
                *(unsigned*)(Ch + (size_t) r0     *ldc + c) = *(unsigned*)&h0;
                *(unsigned*)(Ch + (size_t)(r0 + 8)*ldc + c) = *(unsigned*)&h1;
            }
        }
    }
}

// ---------------- host ----------------
static float* sym(const void* s) {
    void* p = nullptr;
    cudaGetSymbolAddress(&p, s);
    return (float*)p;
}
static __nv_bfloat16* symh(const void* s) {
    void* p = nullptr;
    cudaGetSymbolAddress(&p, s);
    return (__nv_bfloat16*)p;
}

extern "C" void kernel_launch(void* const* d_in, const int* in_sizes, int n_in,
                              void* d_out, int out_size) {
    const float* spt       = (const float*)d_in[0];
    const float* qry       = (const float*)d_in[1];
    const float* conv_w    = (const float*)d_in[2];
    const float* conv_b    = (const float*)d_in[3];
    const float* ln_w      = (const float*)d_in[4];
    const float* ln_b      = (const float*)d_in[5];
    const float* in_proj_w = (const float*)d_in[6];
    const float* conv1d_w  = (const float*)d_in[7];
    const float* conv1d_b  = (const float*)d_in[8];
    const float* x_proj_w  = (const float*)d_in[9];
    const float* dt_proj_w = (const float*)d_in[10];
    const float* dt_proj_b = (const float*)d_in[11];
    const float* A_log     = (const float*)d_in[12];
    const float* D_skip    = (const float*)d_in[13];
    const float* out_proj_w= (const float*)d_in[14];
    const float* mlp_a_w   = (const float*)d_in[15];
    const float* mlp_a_b   = (const float*)d_in[16];
    const float* mlp_b_w   = (const float*)d_in[17];
    const float* mlp_b_b   = (const float*)d_in[18];
    float* out = (float*)d_out;

    float* p_conv = sym(g_conv);
    float* p_F    = sym(g_F);
    float* p_xz   = sym(g_xz);
    float* p_dbc  = sym(g_dbc);
    float* p_dt   = sym(g_dt);
    float* p_m    = sym(g_m);
    float* p_fts2 = sym(g_fts2);
    __nv_bfloat16* ph_fts0 = symh(h_fts0);
    __nv_bfloat16* ph_wcat = symh(h_wcat);
    __nv_bfloat16* ph_inw  = symh(h_inw);
    __nv_bfloat16* ph_xw   = symh(h_xw);
    __nv_bfloat16* ph_dtw  = symh(h_dtw);
    __nv_bfloat16* ph_outw = symh(h_outw);
    __nv_bfloat16* ph_F    = symh(h_F);
    __nv_bfloat16* ph_xact = symh(h_xact);
    __nv_bfloat16* ph_dbc  = symh(h_dbc);
    __nv_bfloat16* ph_ys   = symh(h_ys);

    cudaFuncSetAttribute(gemm_h, cudaFuncAttributeMaxDynamicSharedMemorySize, GSMEM);

    // 0. precision conversions (weights + input concat)
    k_concat_h<<<(MROWS*CDIM/4 + 255)/256, 256>>>(spt, qry);
    k_wcat_h<<<(CDIM*KCAT + 255)/256, 256>>>(conv_w);
    k_cvt<<<(2*DI*CDIM/4 + 255)/256, 256>>>(in_proj_w, ph_inw, 2*DI*CDIM/4);
    k_cvt<<<(64*DI/4 + 255)/256, 256>>>(x_proj_w, ph_xw, 64*DI/4);
    k_cvt<<<(DI*DTR/4 + 255)/256, 256>>>(dt_proj_w, ph_dtw, DI*DTR/4);
    k_cvt<<<(CDIM*DI/4 + 255)/256, 256>>>(out_proj_w, ph_outw, CDIM*DI/4);

    // 1. dense conv (fused im2col): (8192,1536)x(512,1536)^T -> conv (fp32)
    gemm_h<<<dim3(CDIM/TBN, MROWS/TBM), 256, GSMEM>>>(
        MROWS, CDIM, KCAT, ph_fts0, 512, ph_wcat, KCAT,
        p_conv, CDIM, nullptr, conv_b, 0, 1);
    // 2. LN + relu -> F (fp32 + bf16)
    k_ln<<<MROWS, 128>>>(p_conv, nullptr, ln_w, ln_b, p_F, ph_F, 1);
    // 3. in_proj: (8192,512)x(2048,512)^T -> xz (fp32)
    gemm_h<<<dim3(2*DI/TBN, MROWS/TBM), 256, GSMEM>>>(
        MROWS, 2*DI, CDIM, ph_F, CDIM, ph_inw, CDIM,
        p_xz, 2*DI, nullptr, nullptr, 0, 0);
    // 4. depthwise conv + silu -> xact (fp32 + bf16)
    k_dwconv<<<(MROWS*(DI/4) + 255)/256, 256>>>(conv1d_w, conv1d_b);
    // 5. x_proj: (8192,1024)x(64,1024)^T -> dbc (fp32 + bf16)
    gemm_h<<<dim3(1, MROWS/TBM), 256, GSMEM>>>(
        MROWS, 64, DI, ph_xact, DI, ph_xw, DI,
        p_dbc, 64, ph_dbc, nullptr, 0, 0);
    // 6. dt_proj + softplus: (8192,32)x(1024,32)^T -> dt (fp32)
    gemm_h<<<dim3(DI/TBN, MROWS/TBM), 256, GSMEM>>>(
        MROWS, DI, DTR, ph_dbc, 64, ph_dtw, DTR,
        p_dt, DI, nullptr, dt_proj_b, 1, 0);
    // 7. selective scan -> ys (bf16)
    k_scan<<<dim3(DI/256, BB), 256>>>(A_log, D_skip);
    // 8. out_proj: (8192,1024)x(512,1024)^T -> m (fp32)
    gemm_h<<<dim3(CDIM/TBN, MROWS/TBM), 256, GSMEM>>>(
        MROWS, CDIM, DI, ph_ys, DI, ph_outw, DI,
        p_m, CDIM, nullptr, nullptr, 0, 0);
    // 9. residual + LN -> fts2
    k_ln<<<MROWS, 128>>>(p_m, p_F, ln_w, ln_b, p_fts2, nullptr, 0);
    // 10/11. MLP head -> sigmoid
    k_coff<<<MROWS, 128>>>(mlp_a_w, mlp_a_b);
    k_out<<<BB, 128>>>(mlp_b_w, mlp_b_b, out);
}

// round 17
// speedup vs baseline: 4.4710x; 1.0697x over previous
#include <cuda_runtime.h>
#include <cuda_bf16.h>
#include <math.h>

#define BB   64
#define LLEN 128
#define CDIM 512
#define DI   1024
#define DS   16
#define DTR  32
#define MROWS 8192
#define KCAT  1536

// ---------------- fp32 scratch ----------------
__device__ float g_conv[MROWS*CDIM];
__device__ float g_F   [MROWS*CDIM];
__device__ float g_z   [MROWS*DI];
__device__ float g_xact[MROWS*DI];
__device__ float g_dbc [MROWS*64];
__device__ float g_dt  [MROWS*DI];
__device__ float g_m   [MROWS*CDIM];
__device__ float g_fts2[MROWS*CDIM];
__device__ float g_coff[MROWS];

// ---------------- bf16 scratch ----------------
__device__ __align__(16) __nv_bfloat16 h_fts0[MROWS*CDIM];
__device__ __align__(16) __nv_bfloat16 h_wcat[CDIM*KCAT];
__device__ __align__(16) __nv_bfloat16 h_inw [2*DI*CDIM];
__device__ __align__(16) __nv_bfloat16 h_xw  [64*DI];
__device__ __align__(16) __nv_bfloat16 h_dtw [DI*DTR];
__device__ __align__(16) __nv_bfloat16 h_outw[CDIM*DI];
__device__ __align__(16) __nv_bfloat16 h_F   [MROWS*CDIM];
__device__ __align__(16) __nv_bfloat16 h_xact[MROWS*DI];
__device__ __align__(16) __nv_bfloat16 h_dbc [MROWS*64];
__device__ __align__(16) __nv_bfloat16 h_ys  [MROWS*DI];

// ---------------- small helpers ----------------
__device__ __forceinline__ uint2 f4_to_bf4(float4 v) {
    __nv_bfloat162 p0 = __float22bfloat162_rn(make_float2(v.x, v.y));
    __nv_bfloat162 p1 = __float22bfloat162_rn(make_float2(v.z, v.w));
    return make_uint2(*(unsigned*)&p0, *(unsigned*)&p1);
}

// all 4 weight matrices fp32 -> bf16 in one launch (quad-granular)
#define Q_IN  262144   // 2*DI*CDIM/4
#define Q_XW  16384    // 64*DI/4
#define Q_DTW 8192     // DI*DTR/4
#define Q_OUT 131072   // CDIM*DI/4
#define Q_ALL (Q_IN + Q_XW + Q_DTW + Q_OUT)
__global__ void k_cvt_all(const float* __restrict__ w_in, const float* __restrict__ w_x,
                          const float* __restrict__ w_dt, const float* __restrict__ w_out) {
    int i = blockIdx.x * blockDim.x + threadIdx.x;
    if (i < Q_IN) { ((uint2*)h_inw)[i] = f4_to_bf4(((const float4*)w_in)[i]); return; }
    i -= Q_IN;
    if (i < Q_XW) { ((uint2*)h_xw)[i] = f4_to_bf4(((const float4*)w_x)[i]); return; }
    i -= Q_XW;
    if (i < Q_DTW) { ((uint2*)h_dtw)[i] = f4_to_bf4(((const float4*)w_dt)[i]); return; }
    i -= Q_DTW;
    if (i < Q_OUT) { ((uint2*)h_outw)[i] = f4_to_bf4(((const float4*)w_out)[i]); }
}

// concat(spt,qry) reshaped -> h_fts0 bf16
__global__ void k_concat_h(const float* __restrict__ spt, const float* __restrict__ qry) {
    int i4 = blockIdx.x * blockDim.x + threadIdx.x;
    if (i4 >= MROWS*CDIM/4) return;
    int idx = i4 << 2;
    int b = idx >> 16, r = idx & 65535;
    float4 v = (r < 32768) ? *(const float4*)(spt + (size_t)b*32768 + r)
                           : *(const float4*)(qry + (size_t)b*32768 + r - 32768);
    ((uint2*)h_fts0)[i4] = f4_to_bf4(v);
}

// Wcat[o, k*512+i] = conv_w[o, i, k]  (bf16)
__global__ void k_wcat_h(const float* __restrict__ cw) {
    int idx = blockIdx.x * blockDim.x + threadIdx.x;
    if (idx >= CDIM*KCAT) return;
    int o = idx / KCAT, kk = idx % KCAT;
    int k = kk >> 9, i = kk & 511;
    h_wcat[idx] = __float2bfloat16(cw[o*KCAT + i*3 + k]);
}

// LayerNorm over 512 ch; optional residual/relu; optional bf16 copy out.
__global__ __launch_bounds__(128) void k_ln(const float* __restrict__ x,
                                            const float* __restrict__ res,
                                            const float* __restrict__ w,
                                            const float* __restrict__ bb,
                                            float* __restrict__ out,
                                            __nv_bfloat16* __restrict__ outh,
                                            int relu)
{
    int row = blockIdx.x;
    int t = threadIdx.x;
    float4 a = ((const float4*)(x + (size_t)row*CDIM))[t];
    if (res) {
        float4 r4 = ((const float4*)(res + (size_t)row*CDIM))[t];
        a.x += r4.x; a.y += r4.y; a.z += r4.z; a.w += r4.w;
    }
    float s = a.x + a.y + a.z + a.w;
    float q = a.x*a.x + a.y*a.y + a.z*a.z + a.w*a.w;
    __shared__ float shs[4], shq[4];
    int lane = t & 31, wid = t >> 5;
    #pragma unroll
    for (int o = 16; o; o >>= 1) {
        s += __shfl_xor_sync(0xffffffffu, s, o);
        q += __shfl_xor_sync(0xffffffffu, q, o);
    }
    if (lane == 0) { shs[wid] = s; shq[wid] = q; }
    __syncthreads();
    s = shs[0] + shs[1] + shs[2] + shs[3];
    q = shq[0] + shq[1] + shq[2] + shq[3];
    float mu  = s * (1.f/512.f);
    float var = q * (1.f/512.f) - mu*mu;
    float inv = rsqrtf(var + 1e-5f);
    float4 w4 = ((const float4*)w)[t];
    float4 b4 = ((const float4*)bb)[t];
    float4 o4;
    o4.x = (a.x - mu)*inv*w4.x + b4.x;
    o4.y = (a.y - mu)*inv*w4.y + b4.y;
    o4.z = (a.z - mu)*inv*w4.z + b4.z;
    o4.w = (a.w - mu)*inv*w4.w + b4.w;
    if (relu) {
        o4.x = fmaxf(o4.x, 0.f); o4.y = fmaxf(o4.y, 0.f);
        o4.z = fmaxf(o4.z, 0.f); o4.w = fmaxf(o4.w, 0.f);
    }
    ((float4*)(out + (size_t)row*CDIM))[t] = o4;
    if (outh) ((uint2*)(outh + (size_t)row*CDIM))[t] = f4_to_bf4(o4);
}

// selective scan (+D skip, +silu(z) gate) -> bf16 ys. Power-chain fast path.
__global__ __launch_bounds__(256) void k_scan(const float* __restrict__ A_log,
                                              const float* __restrict__ D_skip)
{
    __shared__ float sB[LLEN][DS];
    __shared__ float sC[LLEN][DS];
    int b = blockIdx.y;
    int d = blockIdx.x * 256 + threadIdx.x;
    for (int i = threadIdx.x; i < LLEN*DS; i += 256) {
        int l = i >> 4, n = i & 15;
        sB[l][n] = g_dbc[(size_t)((b<<7)+l)*64 + 32 + n];
        sC[l][n] = g_dbc[(size_t)((b<<7)+l)*64 + 48 + n];
    }
    __syncthreads();
    float Ad[DS];
    #pragma unroll
    for (int n = 0; n < DS; n++) Ad[n] = -__expf(A_log[d*DS + n]);
    float Dv = D_skip[d];
    bool chain = true;
    #pragma unroll
    for (int n = 1; n < DS; n++)
        chain = chain && (fabsf(Ad[n] - (n+1)*Ad[0]) <= 1e-4f*(float)(n+1));
    float h[DS];
    #pragma unroll
    for (int n = 0; n < DS; n++) h[n] = 0.f;

    if (chain) {
        for (int l = 0; l < LLEN; l++) {
            size_t off = (size_t)(b<<7) + l;
            float dtv = g_dt  [off*DI + d];
            float xv  = g_xact[off*DI + d];
            float zv  = g_z   [off*DI + d];
            float dx = dtv * xv;
            float p = __expf(dtv * Ad[0]);
            float wmul = 1.f;
            float acc = 0.f;
            #pragma unroll
            for (int n = 0; n < DS; n++) {
                wmul *= p;
                h[n] = wmul * h[n] + dx * sB[l][n];
                acc += h[n] * sC[l][n];
            }
            float yv = acc + xv * Dv;
            float sz = zv / (1.f + __expf(-zv));
            h_ys[off*DI + d] = __float2bfloat16(yv * sz);
        }
    } else {
        for (int l = 0; l < LLEN; l++) {
            size_t off = (size_t)(b<<7) + l;
            float dtv = g_dt  [off*DI + d];
            float xv  = g_xact[off*DI + d];
            float zv  = g_z   [off*DI + d];
            float dx = dtv * xv;
            float acc = 0.f;
            #pragma unroll
            for (int n = 0; n < DS; n++) {
                h[n] = __expf(dtv * Ad[n]) * h[n] + dx * sB[l][n];
                acc += h[n] * sC[l][n];
            }
            float yv = acc + xv * Dv;
            float sz = zv / (1.f + __expf(-zv));
            h_ys[off*DI + d] = __float2bfloat16(yv * sz);
        }
    }
}

__global__ void k_coff(const float* __restrict__ aw, const float* __restrict__ ab) {
    int row = blockIdx.x, t = threadIdx.x;
    const float* xp = g_fts2 + (size_t)row * CDIM;
    float s = 0.f;
    #pragma unroll
    for (int i = 0; i < 4; i++) s += xp[t + i*128] * aw[t + i*128];
    __shared__ float sh[4];
    int lane = t & 31, wid = t >> 5;
    #pragma unroll
    for (int o = 16; o; o >>= 1) s += __shfl_xor_sync(0xffffffffu, s, o);
    if (lane == 0) sh[wid] = s;
    __syncthreads();
    if (t == 0) g_coff[row] = sh[0] + sh[1] + sh[2] + sh[3] + ab[0];
}

__global__ void k_out(const float* __restrict__ bw, const float* __restrict__ bbias,
                      float* __restrict__ out) {
    int b = blockIdx.x, t = threadIdx.x;
    float s = g_coff[b*128 + t] * bw[t];
    __shared__ float sh[4];
    int lane = t & 31, wid = t >> 5;
    #pragma unroll
    for (int o = 16; o; o >>= 1) s += __shfl_xor_sync(0xffffffffu, s, o);
    if (lane == 0) sh[wid] = s;
    __syncthreads();
    if (t == 0) {
        float v = sh[0] + sh[1] + sh[2] + sh[3] + bbias[0];
        out[b] = 1.f / (1.f + __expf(-v));
    }
}

// ============== bf16 GEMM, cp.async 4-stage pipeline, ldmatrix ===============
// C[M,N] = A[M,K]*B[N,K]^T. A,B bf16 gmem; C fp32 (+ optional bf16 copy).
// 128x128 tile, BK=32, 8 warps (4m x 2n), warp tile 32x64, mma.m16n8k16.
// convMode=1: A = h_fts0 with fused im2col (shift = k0>>9). N-guard for N<128.
// convMode=2: in_proj fusion. TBM row-block = one batch's full sequence.
//   x-half tiles (bx<8): stage acc to smem, 4-tap causal conv + SiLU
//   -> g_xact/h_xact.  z-half tiles (bx>=8): write g_z fp32.
// act=1: softplus epilogue.

#define TBM 128
#define TBN 128
#define TBK 32
#define ROWB 80                 // bytes per smem row (64 data + 16 pad)
#define ASTAGE (TBM*ROWB)       // 10240
#define STAGES 4
#define GSMEM (2*STAGES*ASTAGE) // 81920

__device__ __forceinline__ void cp16(unsigned dst, const void* src, int sz) {
    asm volatile("cp.async.cg.shared.global [%0], [%1], 16, %2;"
                 :: "r"(dst), "l"(src), "r"(sz) : "memory");
}
__device__ __forceinline__ void cp_commit() {
    asm volatile("cp.async.commit_group;" ::: "memory");
}
__device__ __forceinline__ void cp_wait2() {
    asm volatile("cp.async.wait_group 2;" ::: "memory");
}
__device__ __forceinline__ void ldsm_x4(unsigned addr, unsigned &r0, unsigned &r1,
                                        unsigned &r2, unsigned &r3) {
    asm volatile("ldmatrix.sync.aligned.m8n8.x4.shared.b16 {%0,%1,%2,%3}, [%4];"
                 : "=r"(r0), "=r"(r1), "=r"(r2), "=r"(r3) : "r"(addr));
}

__global__ __launch_bounds__(256, 2) void gemm_h(
    int M, int N, int K,
    const __nv_bfloat16* __restrict__ A, int lda,
    const __nv_bfloat16* __restrict__ B, int ldb,
    float* __restrict__ C, int ldc,
    __nv_bfloat16* __restrict__ Ch,
    const float* __restrict__ bias, int act, int convMode,
    const float* __restrict__ cw1, const float* __restrict__ cb1)
{
    extern __shared__ __align__(16) unsigned char dynsm[];
    const unsigned aS = (unsigned)__cvta_generic_to_shared(dynsm);
    const unsigned bS = aS + STAGES*ASTAGE;

    const int tid  = threadIdx.x;
    const int lane = tid & 31;
    const int wid  = tid >> 5;
    const int wm   = wid & 3;
    const int wn   = wid >> 2;
    const int bx = blockIdx.x, by = blockIdx.y;

    float acc[2][8][4];
    #pragma unroll
    for (int i = 0; i < 2; i++)
        #pragma unroll
        for (int j = 0; j < 8; j++)
            #pragma unroll
            for (int v = 0; v < 4; v++) acc[i][j][v] = 0.f;

    // ldmatrix base addresses (stage 0, ks 0)
    const int g  = lane >> 3;
    const int lr = lane & 7;
    unsigned aAddr[2], bAddr[4];
    #pragma unroll
    for (int mt = 0; mt < 2; mt++) {
        int row = wm*32 + mt*16 + lr + ((g & 1) << 3);
        aAddr[mt] = aS + row*ROWB + ((g >> 1) << 4);
    }
    #pragma unroll
    for (int p = 0; p < 4; p++) {
        int row = wn*64 + p*16 + lr + ((g >> 1) << 3);
        bAddr[p] = bS + row*ROWB + ((g & 1) << 4);
    }

    auto issue = [&](int kt, int buf) {
        int k0 = kt * TBK;
        #pragma unroll
        for (int i = 0; i < 2; i++) {
            int p   = tid + i*256;   // 0..511
            int row = p >> 2;        // 0..127
            int seg = p & 3;         // 16B segment
            // A
            const __nv_bfloat16* asrc = A;
            int asz = 16;
            if (convMode != 1) {
                asrc = A + (size_t)(by*TBM + row)*lda + k0 + seg*8;
            } else {
                int m  = by*TBM + row;
                int l  = m & 127;
                int b  = m >> 7;
                int lp = l + (k0 >> 9) - 1;
                if ((unsigned)lp < 128u)
                    asrc = A + ((size_t)(b << 7) + lp)*512 + (k0 & 511) + seg*8;
                else
                    asz = 0;
            }
            cp16(aS + buf*ASTAGE + row*ROWB + seg*16, asrc, asz);
            // B
            int nrow = bx*TBN + row;
            const __nv_bfloat16* bsrc = B;
            int bsz = 16;
            if (nrow < N) bsrc = B + (size_t)nrow*ldb + k0 + seg*8;
            else          bsz = 0;
            cp16(bS + buf*ASTAGE + row*ROWB + seg*16, bsrc, bsz);
        }
    };

    const int KT = K / TBK;
    #pragma unroll
    for (int s = 0; s < STAGES-1; s++) {
        if (s < KT) issue(s, s);
        cp_commit();
    }

    for (int kt = 0; kt < KT; kt++) {
        int buf = kt & (STAGES-1);
        cp_wait2();
        __syncthreads();

        #pragma unroll
        for (int ks = 0; ks < 2; ks++) {
            unsigned off = buf*ASTAGE + ks*32;
            unsigned af[2][4], bf[8][2];
            ldsm_x4(aAddr[0] + off, af[0][0], af[0][1], af[0][2], af[0][3]);
            ldsm_x4(aAddr[1] + off, af[1][0], af[1][1], af[1][2], af[1][3]);
            #pragma unroll
            for (int p = 0; p < 4; p++)
                ldsm_x4(bAddr[p] + off, bf[2*p][0], bf[2*p][1],
                                        bf[2*p+1][0], bf[2*p+1][1]);
            #pragma unroll
            for (int mt = 0; mt < 2; mt++)
                #pragma unroll
                for (int nt = 0; nt < 8; nt++) {
                    asm volatile(
                        "mma.sync.aligned.m16n8k16.row.col.f32.bf16.bf16.f32 "
                        "{%0,%1,%2,%3},{%4,%5,%6,%7},{%8,%9},{%0,%1,%2,%3};"
                        : "+f"(acc[mt][nt][0]), "+f"(acc[mt][nt][1]),
                          "+f"(acc[mt][nt][2]), "+f"(acc[mt][nt][3])
                        : "r"(af[mt][0]), "r"(af[mt][1]),
                          "r"(af[mt][2]), "r"(af[mt][3]),
                          "r"(bf[nt][0]), "r"(bf[nt][1]));
                }
        }

        int nk = kt + STAGES - 1;
        if (nk < KT) issue(nk, nk & (STAGES-1));
        cp_commit();
    }

    // ---------------- epilogues ----------------
    if (convMode == 2) {
        __syncthreads();   // all smem reads of the pipeline are done
        if (bx < 8) {
            // x half: stage acc to smem, causal conv + SiLU
            float* sx = (float*)dynsm;   // [128][129] fp32 = 66048 B
            #pragma unroll
            for (int mt = 0; mt < 2; mt++) {
                int rl = wm*32 + mt*16 + (lane >> 2);
                #pragma unroll
                for (int nt = 0; nt < 8; nt++) {
                    int cl = wn*64 + nt*8 + 2*(lane & 3);
                    sx[ rl     *129 + cl    ] = acc[mt][nt][0];
                    sx[ rl     *129 + cl + 1] = acc[mt][nt][1];
                    sx[(rl + 8)*129 + cl    ] = acc[mt][nt][2];
                    sx[(rl + 8)*129 + cl + 1] = acc[mt][nt][3];
                }
            }
            __syncthreads();
            int c    = tid & 127;
            int half = tid >> 7;        // 0 or 1: rows 0..63 / 64..127
            int cg   = bx*TBN + c;      // global channel < 1024
            float4 wv = *(const float4*)(cw1 + cg*4);
            float bc  = cb1[cg];
            float xm3 = 0.f, xm2 = 0.f, xm1 = 0.f;
            if (half) {
                xm3 = sx[61*129 + c];
                xm2 = sx[62*129 + c];
                xm1 = sx[63*129 + c];
            }
            int l0 = half*64;
            #pragma unroll 4
            for (int l = l0; l < l0 + 64; l++) {
                float xl = sx[l*129 + c];
                float a = fmaf(wv.x, xm3, fmaf(wv.y, xm2,
                          fmaf(wv.z, xm1, fmaf(wv.w, xl, bc))));
                float sv = a / (1.f + __expf(-a));
                size_t mi = (size_t)(by*TBM + l)*DI + cg;
                g_xact[mi] = sv;
                h_xact[mi] = __float2bfloat16(sv);
                xm3 = xm2; xm2 = xm1; xm1 = xl;
            }
        } else {
            // z half: plain fp32 store into g_z
            #pragma unroll
            for (int mt = 0; mt < 2; mt++) {
                int r0 = by*TBM + wm*32 + mt*16 + (lane >> 2);
                #pragma unroll
                for (int nt = 0; nt < 8; nt++) {
                    int cz = bx*TBN + wn*64 + nt*8 + 2*(lane & 3) - 1024;
                    *(float2*)(&g_z[(size_t)r0*DI + cz]) =
                        make_float2(acc[mt][nt][0], acc[mt][nt][1]);
                    *(float2*)(&g_z[(size_t)(r0+8)*DI + cz]) =
                        make_float2(acc[mt][nt][2], acc[mt][nt][3]);
                }
            }
        }
        return;
    }

    #pragma unroll
    for (int mt = 0; mt < 2; mt++) {
        int r0 = by*TBM + wm*32 + mt*16 + (lane >> 2);
        #pragma unroll
        for (int nt = 0; nt < 8; nt++) {
            int c = bx*TBN + wn*64 + nt*8 + 2*(lane & 3);
            if (c >= N) continue;
            float bb0 = bias ? bias[c]   : 0.f;
            float bb1 = bias ? bias[c+1] : 0.f;
            float v00 = acc[mt][nt][0] + bb0, v01 = acc[mt][nt][1] + bb1;
            float v10 = acc[mt][nt][2] + bb0, v11 = acc[mt][nt][3] + bb1;
            if (act == 1) {
                v00 = (v00 > 20.f) ? v00 : log1pf(__expf(v00));
                v01 = (v01 > 20.f) ? v01 : log1pf(__expf(v01));
                v10 = (v10 > 20.f) ? v10 : log1pf(__expf(v10));
                v11 = (v11 > 20.f) ? v11 : log1pf(__expf(v11));
            }
            *(float2*)(C + (size_t) r0     *ldc + c) = make_float2(v00, v01);
            *(float2*)(C + (size_t)(r0 + 8)*ldc + c) = make_float2(v10, v11);
            if (Ch) {
                __nv_bfloat162 h0 = __float22bfloat162_rn(make_float2(v00, v01));
                __nv_bfloat162 h1 = __float22bfloat162_rn(make_float2(v10, v11));
                *(unsigned*)(Ch + (size_t) r0     *ldc + c) = *(unsigned*)&h0;
                *(unsigned*)(Ch + (size_t)(r0 + 8)*ldc + c) = *(unsigned*)&h1;
            }
        }
    }
}

// ---------------- host ----------------
static float* sym(const void* s) {
    void* p = nullptr;
    cudaGetSymbolAddress(&p, s);
    return (float*)p;
}
static __nv_bfloat16* symh(const void* s) {
    void* p = nullptr;
    cudaGetSymbolAddress(&p, s);
    return (__nv_bfloat16*)p;
}

extern "C" void kernel_launch(void* const* d_in, const int* in_sizes, int n_in,
                              void* d_out, int out_size) {
    const float* spt       = (const float*)d_in[0];
    const float* qry       = (const float*)d_in[1];
    const float* conv_w    = (const float*)d_in[2];
    const float* conv_b    = (const float*)d_in[3];
    const float* ln_w      = (const float*)d_in[4];
    const float* ln_b      = (const float*)d_in[5];
    const float* in_proj_w = (const float*)d_in[6];
    const float* conv1d_w  = (const float*)d_in[7];
    const float* conv1d_b  = (const float*)d_in[8];
    const float* x_proj_w  = (const float*)d_in[9];
    const float* dt_proj_w = (const float*)d_in[10];
    const float* dt_proj_b = (const float*)d_in[11];
    const float* A_log     = (const float*)d_in[12];
    const float* D_skip    = (const float*)d_in[13];
    const float* out_proj_w= (const float*)d_in[14];
    const float* mlp_a_w   = (const float*)d_in[15];
    const float* mlp_a_b   = (const float*)d_in[16];
    const float* mlp_b_w   = (const float*)d_in[17];
    const float* mlp_b_b   = (const float*)d_in[18];
    float* out = (float*)d_out;

    float* p_conv = sym(g_conv);
    float* p_F    = sym(g_F);
    float* p_dbc  = sym(g_dbc);
    float* p_dt   = sym(g_dt);
    float* p_m    = sym(g_m);
    float* p_fts2 = sym(g_fts2);
    __nv_bfloat16* ph_fts0 = symh(h_fts0);
    __nv_bfloat16* ph_wcat = symh(h_wcat);
    __nv_bfloat16* ph_inw  = symh(h_inw);
    __nv_bfloat16* ph_xw   = symh(h_xw);
    __nv_bfloat16* ph_dtw  = symh(h_dtw);
    __nv_bfloat16* ph_outw = symh(h_outw);
    __nv_bfloat16* ph_F    = symh(h_F);
    __nv_bfloat16* ph_xact = symh(h_xact);
    __nv_bfloat16* ph_dbc  = symh(h_dbc);
    __nv_bfloat16* ph_ys   = symh(h_ys);

    cudaFuncSetAttribute(gemm_h, cudaFuncAttributeMaxDynamicSharedMemorySize, GSMEM);

    // 0. precision conversions (inputs + all weights)
    k_concat_h<<<(MROWS*CDIM/4 + 255)/256, 256>>>(spt, qry);
    k_wcat_h<<<(CDIM*KCAT + 255)/256, 256>>>(conv_w);
    k_cvt_all<<<(Q_ALL + 255)/256, 256>>>(in_proj_w, x_proj_w, dt_proj_w, out_proj_w);

    // 1. dense conv (fused im2col): (8192,1536)x(512,1536)^T -> conv (fp32)
    gemm_h<<<dim3(CDIM/TBN, MROWS/TBM), 256, GSMEM>>>(
        MROWS, CDIM, KCAT, ph_fts0, 512, ph_wcat, KCAT,
        p_conv, CDIM, nullptr, conv_b, 0, 1, nullptr, nullptr);
    // 2. LN + relu -> F (fp32 + bf16)
    k_ln<<<MROWS, 128>>>(p_conv, nullptr, ln_w, ln_b, p_F, ph_F, 1);
    // 3. in_proj + fused dwconv/silu (x half) + z store:
    //    (8192,512)x(2048,512)^T -> xact (fp32+bf16), z (fp32)
    gemm_h<<<dim3(2*DI/TBN, MROWS/TBM), 256, GSMEM>>>(
        MROWS, 2*DI, CDIM, ph_F, CDIM, ph_inw, CDIM,
        nullptr, 0, nullptr, nullptr, 0, 2, conv1d_w, conv1d_b);
    // 4. x_proj: (8192,1024)x(64,1024)^T -> dbc (fp32 + bf16)
    gemm_h<<<dim3(1, MROWS/TBM), 256, GSMEM>>>(
        MROWS, 64, DI, ph_xact, DI, ph_xw, DI,
        p_dbc, 64, ph_dbc, nullptr, 0, 0, nullptr, nullptr);
    // 5. dt_proj + softplus: (8192,32)x(1024,32)^T -> dt (fp32)
    gemm_h<<<dim3(DI/TBN, MROWS/TBM), 256, GSMEM>>>(
        MROWS, DI, DTR, ph_dbc, 64, ph_dtw, DTR,
        p_dt, DI, nullptr, dt_proj_b, 1, 0, nullptr, nullptr);
    // 6. selective scan -> ys (bf16)
    k_scan<<<dim3(DI/256, BB), 256>>>(A_log, D_skip);
    // 7. out_proj: (8192,1024)x(512,1024)^T -> m (fp32)
    gemm_h<<<dim3(CDIM/TBN, MROWS/TBM), 256, GSMEM>>>(
        MROWS, CDIM, DI, ph_ys, DI, ph_outw, DI,
        p_m, CDIM, nullptr, nullptr, 0, 0, nullptr, nullptr);
    // 8. residual + LN -> fts2
    k_ln<<<MROWS, 128>>>(p_m, p_F, ln_w, ln_b, p_fts2, nullptr, 0);
    // 9/10. MLP head -> sigmoid
    k_coff<<<MROWS, 128>>>(mlp_a_w, mlp_a_b);
    k_out<<<BB, 128>>>(mlp_b_w, mlp_b_b, out);
}